// round 7
// baseline (speedup 1.0000x reference)
#include <cuda_runtime.h>
#include <stdint.h>

#define BATCH 8
#define HW    4096
#define CDIM  384
#define KSEL  128

#define FEAT_N (BATCH * HW * CDIM)   // 12582912
#define MASK_N (BATCH * HW)          // 32768
#define BK_N   (BATCH * KSEL)        // 1024

// ---------------- scratch (device globals: no allocations allowed) ----------
__device__ float g_f1[FEAT_N];   // normalized, masked feature1
__device__ float g_f2[FEAT_N];   // normalized, masked feature2
__device__ float g_sq1[MASK_N];
__device__ float g_sq2[MASK_N];
// packed argmin state: high 32 bits = float bits of d (>=0), low 32 = index
__device__ unsigned long long g_key1[MASK_N];  // argmin over j (match1)
__device__ unsigned long long g_key2[MASK_N];  // argmin over i (match2)

// ---------------- init ------------------------------------------------------
__global__ void init_keys_kernel() {
    int t = blockIdx.x * blockDim.x + threadIdx.x;
    if (t < MASK_N) { g_key1[t] = ~0ULL; g_key2[t] = ~0ULL; }
}

// ---------------- normalize: f / ||f||, zero masked; record sum(y^2) --------
__global__ void normalize_kernel(const float* __restrict__ f,
                                 const int* __restrict__ mask, int which) {
    int token = blockIdx.x * 8 + (threadIdx.x >> 5);
    int lane  = threadIdx.x & 31;
    if (token >= MASK_N) return;
    const float* src = f + (size_t)token * CDIM;
    float v[12];
    float s = 0.f;
#pragma unroll
    for (int q = 0; q < 12; q++) { v[q] = src[lane + 32 * q]; s += v[q] * v[q]; }
#pragma unroll
    for (int o = 16; o; o >>= 1) s += __shfl_xor_sync(0xFFFFFFFFu, s, o);
    float norm = sqrtf(s);
    float m = (mask[token] > 0) ? 1.f : 0.f;
    float* dst = (which ? g_f2 : g_f1) + (size_t)token * CDIM;
    float sq = 0.f;
#pragma unroll
    for (int q = 0; q < 12; q++) {
        float y = m * (v[q] / norm);
        dst[lane + 32 * q] = y;
        sq += y * y;
    }
#pragma unroll
    for (int o = 16; o; o >>= 1) sq += __shfl_xor_sync(0xFFFFFFFFu, sq, o);
    if (lane == 0) (which ? g_sq2 : g_sq1)[token] = sq;
}

// ---------------- tiled GEMM + fused row/col argmin -------------------------
// CTA: 128x128 tile, 256 threads (16x16). Thread tile 8x8 as 2x2 float4 blocks
// (rows 4ty..+3 & 4ty+64..+67, cols 4tx..+3 & 4tx+64..+67) -> LDS.128 fragment
// loads. Smem stored K-transposed: As[kk*132 + row]. Register prefetch of the
// next K=32 chunk overlaps LDG with compute.
#define SROW 132   // row stride (floats): 132*4B = 528B, 16B-aligned

__global__ void __launch_bounds__(256, 2)
argmin_kernel(const int* __restrict__ mask1, const int* __restrict__ mask2) {
    int bt = blockIdx.z, it = blockIdx.y, jt = blockIdx.x;
    __shared__ float As[32 * SROW];
    __shared__ float Bs[32 * SROW];
    __shared__ unsigned long long s_col[8][128];

    const float* A  = g_f1 + ((size_t)bt * HW + it * 128) * CDIM;
    const float* Bp = g_f2 + ((size_t)bt * HW + jt * 128) * CDIM;

    int tid = threadIdx.x;
    int tx = tid & 15, ty = tid >> 4;

    float acc[8][8];
#pragma unroll
    for (int v = 0; v < 8; v++)
#pragma unroll
        for (int u = 0; u < 8; u++) acc[v][u] = 0.f;

    // per-thread load slots: id = tid + r*256 -> row = id>>3, kq = id&7
    int lrow[4], lkq[4];
#pragma unroll
    for (int r = 0; r < 4; r++) { int id = tid + r * 256; lrow[r] = id >> 3; lkq[r] = id & 7; }

    float4 pa[4], pb[4];
    // prefetch chunk 0
#pragma unroll
    for (int r = 0; r < 4; r++) {
        pa[r] = *(const float4*)(A  + (size_t)lrow[r] * CDIM + lkq[r] * 4);
        pb[r] = *(const float4*)(Bp + (size_t)lrow[r] * CDIM + lkq[r] * 4);
    }
    // store chunk 0 (K-transposed)
#pragma unroll
    for (int r = 0; r < 4; r++) {
        int base = lkq[r] * 4 * SROW + lrow[r];
        As[base]            = pa[r].x; As[base + SROW]     = pa[r].y;
        As[base + 2 * SROW] = pa[r].z; As[base + 3 * SROW] = pa[r].w;
        Bs[base]            = pb[r].x; Bs[base + SROW]     = pb[r].y;
        Bs[base + 2 * SROW] = pb[r].z; Bs[base + 3 * SROW] = pb[r].w;
    }
    __syncthreads();

    for (int c = 0; c < 12; c++) {
        if (c < 11) {
            int k0 = (c + 1) * 32;
#pragma unroll
            for (int r = 0; r < 4; r++) {
                pa[r] = *(const float4*)(A  + (size_t)lrow[r] * CDIM + k0 + lkq[r] * 4);
                pb[r] = *(const float4*)(Bp + (size_t)lrow[r] * CDIM + k0 + lkq[r] * 4);
            }
        }
#pragma unroll 8
        for (int kk = 0; kk < 32; kk++) {
            const float* ar = As + kk * SROW;
            const float* br = Bs + kk * SROW;
            float4 a0 = *(const float4*)(ar + 4 * ty);
            float4 a1 = *(const float4*)(ar + 4 * ty + 64);
            float4 b0 = *(const float4*)(br + 4 * tx);
            float4 b1 = *(const float4*)(br + 4 * tx + 64);
            float av[8] = {a0.x, a0.y, a0.z, a0.w, a1.x, a1.y, a1.z, a1.w};
            float bv[8] = {b0.x, b0.y, b0.z, b0.w, b1.x, b1.y, b1.z, b1.w};
#pragma unroll
            for (int v = 0; v < 8; v++)
#pragma unroll
                for (int u = 0; u < 8; u++)
                    acc[v][u] = fmaf(av[v], bv[u], acc[v][u]);
        }
        __syncthreads();
        if (c < 11) {
#pragma unroll
            for (int r = 0; r < 4; r++) {
                int base = lkq[r] * 4 * SROW + lrow[r];
                As[base]            = pa[r].x; As[base + SROW]     = pa[r].y;
                As[base + 2 * SROW] = pa[r].z; As[base + 3 * SROW] = pa[r].w;
                Bs[base]            = pb[r].x; Bs[base + SROW]     = pb[r].y;
                Bs[base + 2 * SROW] = pb[r].z; Bs[base + 3 * SROW] = pb[r].w;
            }
            __syncthreads();
        }
    }

    // ---- epilogue: masks, sq, d = sqrt(max(.,0)) or BIG_DIST ----
    int   m1v[8], m2v[8];
    float sq1v[8], sq2v[8];
    int ibase = bt * HW + it * 128 + 4 * ty;
    int jbase = bt * HW + jt * 128 + 4 * tx;
#pragma unroll
    for (int n = 0; n < 4; n++) {
        m1v[n]      = mask1[ibase + n];        sq1v[n]     = g_sq1[ibase + n];
        m1v[4 + n]  = mask1[ibase + 64 + n];   sq1v[4 + n] = g_sq1[ibase + 64 + n];
        m2v[n]      = mask2[jbase + n];        sq2v[n]     = g_sq2[jbase + n];
        m2v[4 + n]  = mask2[jbase + 64 + n];   sq2v[4 + n] = g_sq2[jbase + 64 + n];
    }

    float dval[8][8];
#pragma unroll
    for (int v = 0; v < 8; v++)
#pragma unroll
        for (int u = 0; u < 8; u++)
            dval[v][u] = (m1v[v] > 0 && m2v[u] > 0)
                ? sqrtf(fmaxf(sq1v[v] + sq2v[u] - 2.f * acc[v][u], 0.f))
                : 1.0e7f;

    // local (within-tile) row/col indices of this thread's 8x8 block
    int rloc[8], cloc[8];
#pragma unroll
    for (int n = 0; n < 4; n++) {
        rloc[n] = 4 * ty + n;  rloc[4 + n] = 64 + 4 * ty + n;
        cloc[n] = 4 * tx + n;  cloc[4 + n] = 64 + 4 * tx + n;
    }

    // --- row argmin (over j) -> g_key1 ---
#pragma unroll
    for (int v = 0; v < 8; v++) {
        unsigned long long best = ~0ULL;
#pragma unroll
        for (int u = 0; u < 8; u++) {
            unsigned j = (unsigned)(jt * 128 + cloc[u]);
            unsigned long long key =
                ((unsigned long long)__float_as_uint(dval[v][u]) << 32) | j;
            best = key < best ? key : best;
        }
#pragma unroll
        for (int o = 1; o < 16; o <<= 1) {   // reduce across tx (16-lane halves)
            unsigned long long oth = __shfl_xor_sync(0xFFFFFFFFu, best, o);
            best = oth < best ? oth : best;
        }
        if (tx == 0)
            atomicMin(&g_key1[bt * HW + it * 128 + rloc[v]], best);
    }

    // --- col argmin (over i) -> g_key2 ---
#pragma unroll
    for (int u = 0; u < 8; u++) {
        unsigned long long best = ~0ULL;
#pragma unroll
        for (int v = 0; v < 8; v++) {
            unsigned i = (unsigned)(it * 128 + rloc[v]);
            unsigned long long key =
                ((unsigned long long)__float_as_uint(dval[v][u]) << 32) | i;
            best = key < best ? key : best;
        }
        unsigned long long oth = __shfl_xor_sync(0xFFFFFFFFu, best, 16); // merge ty pair
        best = oth < best ? oth : best;
        if ((tid & 31) < 16) s_col[tid >> 5][cloc[u]] = best;
    }
    __syncthreads();
    if (tid < 128) {
        unsigned long long best = s_col[0][tid];
#pragma unroll
        for (int w = 1; w < 8; w++) {
            unsigned long long o = s_col[w][tid];
            best = o < best ? o : best;
        }
        atomicMin(&g_key2[bt * HW + jt * 128 + tid], best);
    }
}

// ---------------- cyclic diff + stable top-128 (bitonic) --------------------
// Output written as FLOAT32 (harness __output__ dtype): index values <= 4095
// are exactly representable.
__global__ void topk_kernel(const int* __restrict__ mask1, const int* __restrict__ mask2,
                            const int* __restrict__ backup1, const int* __restrict__ backup2,
                            float* __restrict__ out) {
    int b   = blockIdx.x >> 1;
    int dir = blockIdx.x & 1;
    const unsigned long long* keyF  = dir ? g_key2 : g_key1; // match_fwd
    const unsigned long long* keyBk = dir ? g_key1 : g_key2; // match_bwd
    const int* mSrc   = dir ? mask2   : mask1;
    const int* mDst   = dir ? mask1   : mask2;
    const int* backup = dir ? backup2 : backup1;

    __shared__ unsigned long long keys[HW];   // 32 KB
    __shared__ int s_cnt;
    int tid = threadIdx.x;                    // 512 threads
    if (tid == 0) s_cnt = 0;
    __syncthreads();

    int cnt = 0;
    for (int i = tid; i < HW; i += 512) {
        int srcm = mSrc[b * HW + i];
        cnt += (srcm > 0);
        int mf = (int)(keyF[b * HW + i] & 0xFFFFFFFFull);
        unsigned k32;
        if (srcm > 0 && mDst[b * HW + mf] > 0) {
            int cyc = (int)(keyBk[b * HW + mf] & 0xFFFFFFFFull);
            int dx = (cyc >> 6) - (i >> 6);   // x = idx / 64
            int dy = (cyc & 63) - (i & 63);   // y = idx % 64
            k32 = (unsigned)(dx * dx + dy * dy); // integer d2: same order/ties as fp32 sqrt
        } else {
            k32 = 0x7FFFFFFFu;                // > any real diff  (BIG_DIFF stand-in)
        }
        keys[i] = ((unsigned long long)k32 << 32) | (unsigned)i;
    }
#pragma unroll
    for (int o = 16; o; o >>= 1) cnt += __shfl_xor_sync(0xFFFFFFFFu, cnt, o);
    if ((tid & 31) == 0) atomicAdd(&s_cnt, cnt);
    __syncthreads();

    // bitonic sort ascending over (d2, index) — matches jax.lax.top_k stability
    for (int kk = 2; kk <= HW; kk <<= 1) {
        for (int jj = kk >> 1; jj > 0; jj >>= 1) {
            for (int i = tid; i < HW; i += 512) {
                int ixj = i ^ jj;
                if (ixj > i) {
                    unsigned long long a = keys[i], c = keys[ixj];
                    bool up = ((i & kk) == 0);
                    if ((a > c) == up) { keys[i] = c; keys[ixj] = a; }
                }
            }
            __syncthreads();
        }
    }

    bool useTop = (s_cnt >= KSEL);
    if (tid < KSEL) {
        int idx   = useTop ? (int)(keys[tid] & 0xFFFFFFFFull) : backup[b * KSEL + tid];
        int match = (int)(keyF[b * HW + idx] & 0xFFFFFFFFull);
        int base  = dir * (BATCH * KSEL * 2) + b * (KSEL * 2) + tid * 2;
        out[base]     = (float)idx;
        out[base + 1] = (float)match;
    }
}

// ---------------- launch ----------------------------------------------------
extern "C" void kernel_launch(void* const* d_in, const int* in_sizes, int n_in,
                              void* d_out, int out_size) {
    // Bind inputs by size; accept element counts OR byte counts (no collisions
    // between the 6 classes in either unit). Fall back to dict order.
    const float* f1 = nullptr; const float* f2 = nullptr;
    const int* mask1 = nullptr; const int* mask2 = nullptr;
    const int* bk1 = nullptr; const int* bk2 = nullptr;
    for (int i = 0; i < n_in; i++) {
        long long sz = in_sizes[i];
        if (sz == FEAT_N || sz == (long long)FEAT_N * 4) {
            if (!f1) f1 = (const float*)d_in[i]; else f2 = (const float*)d_in[i];
        } else if (sz == MASK_N || sz == (long long)MASK_N * 4) {
            if (!mask1) mask1 = (const int*)d_in[i]; else mask2 = (const int*)d_in[i];
        } else if (sz == BK_N || sz == (long long)BK_N * 4) {
            if (!bk1) bk1 = (const int*)d_in[i]; else bk2 = (const int*)d_in[i];
        }
    }
    if (!f1 || !f2 || !mask1 || !mask2 || !bk1 || !bk2) {
        // positional fallback: setup_inputs() dict order
        f1    = (const float*)d_in[0];
        f2    = (const float*)d_in[1];
        mask1 = (const int*)d_in[2];
        mask2 = (const int*)d_in[3];
        bk1   = (const int*)d_in[4];
        bk2   = (const int*)d_in[5];
    }
    float* out = (float*)d_out;

    init_keys_kernel<<<(MASK_N + 1023) / 1024, 1024>>>();
    normalize_kernel<<<MASK_N / 8, 256>>>(f1, mask1, 0);
    normalize_kernel<<<MASK_N / 8, 256>>>(f2, mask2, 1);
    dim3 grid(HW / 128, HW / 128, BATCH);
    argmin_kernel<<<grid, 256>>>(mask1, mask2);
    topk_kernel<<<BATCH * 2, 512>>>(mask1, mask2, bk1, bk2, out);
}

// round 9
// speedup vs baseline: 2.3642x; 2.3642x over previous
#include <cuda_runtime.h>
#include <cuda_fp16.h>
#include <stdint.h>

#define BATCH 8
#define HW    4096
#define CDIM  384
#define KSEL  128

#define FEAT_N (BATCH * HW * CDIM)   // 12582912
#define MASK_N (BATCH * HW)          // 32768
#define BK_N   (BATCH * KSEL)        // 1024

#define KC       32                  // k-chunk (halfs)
#define NCHUNK   (CDIM / KC)         // 12
#define STRH     40                  // smem row stride in halfs (80B, ldmatrix conflict-free)
#define TILE_HB  (128 * STRH * 2)    // 10240 bytes per 128x32 half tile
#define BUF_B    (4 * TILE_HB)       // a0,a1,b0,b1 = 40960 per stage
#define EPI_OFF  (2 * BUF_B)         // 81920
#define SMEM_DYN (EPI_OFF + 2048)    // + s_row/s_col (128 u64 each)

// ---------------- scratch (device globals: no allocations allowed) ----------
__device__ __half g_h0a[FEAT_N], g_h1a[FEAT_N];   // f1 = h0 + h1 (fp16 split)
__device__ __half g_h0b[FEAT_N], g_h1b[FEAT_N];   // f2 split
__device__ float g_sq1[MASK_N];
__device__ float g_sq2[MASK_N];
__device__ unsigned long long g_key1[MASK_N];  // argmin over j (match1)
__device__ unsigned long long g_key2[MASK_N];  // argmin over i (match2)

// ---------------- helpers ---------------------------------------------------
__device__ __forceinline__ uint32_t smem_u32(const void* p) {
    uint32_t a;
    asm("{ .reg .u64 t; cvta.to.shared.u64 t, %1; cvt.u32.u64 %0, t; }" : "=r"(a) : "l"(p));
    return a;
}
__device__ __forceinline__ void cp_async16(uint32_t dst, const void* src) {
    asm volatile("cp.async.cg.shared.global [%0], [%1], 16;" :: "r"(dst), "l"(src) : "memory");
}
__device__ __forceinline__ void ldsm4(uint32_t& r0, uint32_t& r1, uint32_t& r2, uint32_t& r3,
                                      uint32_t a) {
    asm volatile("ldmatrix.sync.aligned.m8n8.x4.shared.b16 {%0,%1,%2,%3}, [%4];"
                 : "=r"(r0), "=r"(r1), "=r"(r2), "=r"(r3) : "r"(a));
}
__device__ __forceinline__ void mma16816(float* c, uint32_t a0, uint32_t a1, uint32_t a2,
                                         uint32_t a3, uint32_t b0, uint32_t b1) {
    asm volatile(
        "mma.sync.aligned.m16n8k16.row.col.f32.f16.f16.f32 "
        "{%0,%1,%2,%3}, {%4,%5,%6,%7}, {%8,%9}, {%0,%1,%2,%3};"
        : "+f"(c[0]), "+f"(c[1]), "+f"(c[2]), "+f"(c[3])
        : "r"(a0), "r"(a1), "r"(a2), "r"(a3), "r"(b0), "r"(b1));
}

// ---------------- init ------------------------------------------------------
__global__ void init_keys_kernel() {
    int t = blockIdx.x * blockDim.x + threadIdx.x;
    if (t < MASK_N) { g_key1[t] = ~0ULL; g_key2[t] = ~0ULL; }
}

// ------------- normalize + fp16 2-way split + sum(y^2) ----------------------
__global__ void normalize_kernel(const float* __restrict__ f,
                                 const int* __restrict__ mask, int which) {
    int token = blockIdx.x * 8 + (threadIdx.x >> 5);
    int lane  = threadIdx.x & 31;
    if (token >= MASK_N) return;
    const float* src = f + (size_t)token * CDIM;
    float v[12];
    float s = 0.f;
#pragma unroll
    for (int q = 0; q < 12; q++) { v[q] = src[lane + 32 * q]; s += v[q] * v[q]; }
#pragma unroll
    for (int o = 16; o; o >>= 1) s += __shfl_xor_sync(0xFFFFFFFFu, s, o);
    float norm = sqrtf(s);
    float m = (mask[token] > 0) ? 1.f : 0.f;
    __half* d0 = (which ? g_h0b : g_h0a) + (size_t)token * CDIM;
    __half* d1 = (which ? g_h1b : g_h1a) + (size_t)token * CDIM;
    float sq = 0.f;
#pragma unroll
    for (int q = 0; q < 12; q++) {
        float y = m * (v[q] / norm);
        sq += y * y;
        __half h0 = __float2half_rn(y);
        float  r  = y - __half2float(h0);
        __half h1 = __float2half_rn(r);
        d0[lane + 32 * q] = h0;
        d1[lane + 32 * q] = h1;
    }
#pragma unroll
    for (int o = 16; o; o >>= 1) sq += __shfl_xor_sync(0xFFFFFFFFu, sq, o);
    if (lane == 0) (which ? g_sq2 : g_sq1)[token] = sq;
}

// -------- mma.sync fp16x2-split GEMM (3 products) + fused argmin ------------
// CTA 128x128 tile, 256 threads = 8 warps (2 M x 4 N), warp tile 64x32.
__global__ void __launch_bounds__(256)
mma_argmin_kernel(const int* __restrict__ mask1, const int* __restrict__ mask2) {
    extern __shared__ char smem[];
    int bt = blockIdx.z, it = blockIdx.y, jt = blockIdx.x;
    int tid = threadIdx.x, wid = tid >> 5, lane = tid & 31;
    int warp_m = wid >> 2, warp_n = wid & 3;      // M: 2 x 64 rows, N: 4 x 32 cols

    uint32_t sbase = smem_u32(smem);
    unsigned long long* s_row = (unsigned long long*)(smem + EPI_OFF);
    unsigned long long* s_col = (unsigned long long*)(smem + EPI_OFF + 1024);
    if (tid < 128) { s_row[tid] = ~0ULL; s_col[tid] = ~0ULL; }

    size_t offA = ((size_t)bt * HW + it * 128) * CDIM;
    size_t offB = ((size_t)bt * HW + jt * 128) * CDIM;
    const __half* srcs[4] = { g_h0a + offA, g_h1a + offA, g_h0b + offB, g_h1b + offB };

    // cp.async fill: thread -> tile t = tid>>6, 8 segments of 16B
    int ft = tid >> 6, fs0 = tid & 63;
    const __half* fsrc = srcs[ft];
    uint32_t fdst0 = sbase + ft * TILE_HB;

    float acc[4][4][4];
#pragma unroll
    for (int mf = 0; mf < 4; mf++)
#pragma unroll
        for (int nf = 0; nf < 4; nf++)
#pragma unroll
            for (int v = 0; v < 4; v++) acc[mf][nf][v] = 0.f;

    // fill chunk 0 -> buffer 0
#pragma unroll
    for (int r = 0; r < 8; r++) {
        int s = fs0 + r * 64, row = s >> 2, seg = s & 3;
        cp_async16(fdst0 + row * 80 + seg * 16, fsrc + (size_t)row * CDIM + seg * 8);
    }
    asm volatile("cp.async.commit_group;" ::: "memory");
    asm volatile("cp.async.wait_group 0;" ::: "memory");
    __syncthreads();

    int lrow = lane & 15, lsel = (lane >> 4) << 3;   // ldmatrix lane addressing

    for (int c = 0; c < NCHUNK; c++) {
        uint32_t buf = (uint32_t)(c & 1) * BUF_B;
        if (c < NCHUNK - 1) {
            uint32_t nbuf = (uint32_t)((c + 1) & 1) * BUF_B;
            int k0 = (c + 1) * KC;
#pragma unroll
            for (int r = 0; r < 8; r++) {
                int s = fs0 + r * 64, row = s >> 2, seg = s & 3;
                cp_async16(fdst0 + nbuf + row * 80 + seg * 16,
                           fsrc + (size_t)row * CDIM + k0 + seg * 8);
            }
            asm volatile("cp.async.commit_group;" ::: "memory");
        }
#pragma unroll
        for (int kk = 0; kk < 2; kk++) {         // two k16 steps per chunk
            int kb = kk * 16;
            uint32_t a[2][4][4];
#pragma unroll
            for (int s = 0; s < 2; s++)
#pragma unroll
                for (int mf = 0; mf < 4; mf++) {
                    uint32_t addr = sbase + buf + s * TILE_HB +
                        (uint32_t)(warp_m * 64 + mf * 16 + lrow) * 80 + (kb + lsel) * 2;
                    ldsm4(a[s][mf][0], a[s][mf][1], a[s][mf][2], a[s][mf][3], addr);
                }
            uint32_t b[2][2][4];
#pragma unroll
            for (int s = 0; s < 2; s++)
#pragma unroll
                for (int ng = 0; ng < 2; ng++) {
                    uint32_t addr = sbase + buf + (2 + s) * TILE_HB +
                        (uint32_t)(warp_n * 32 + ng * 16 + lrow) * 80 + (kb + lsel) * 2;
                    ldsm4(b[s][ng][0], b[s][ng][1], b[s][ng][2], b[s][ng][3], addr);
                }
#pragma unroll
            for (int mf = 0; mf < 4; mf++)
#pragma unroll
                for (int nf = 0; nf < 4; nf++) {
                    int ng = nf >> 1, hh = nf & 1;
                    uint32_t b00 = b[0][ng][hh], b01 = b[0][ng][hh + 2];  // split0
                    uint32_t b10 = b[1][ng][hh], b11 = b[1][ng][hh + 2];  // split1
                    float* cc = acc[mf][nf];
                    mma16816(cc, a[0][mf][0], a[0][mf][1], a[0][mf][2], a[0][mf][3], b00, b01);
                    mma16816(cc, a[0][mf][0], a[0][mf][1], a[0][mf][2], a[0][mf][3], b10, b11);
                    mma16816(cc, a[1][mf][0], a[1][mf][1], a[1][mf][2], a[1][mf][3], b00, b01);
                }
        }
        asm volatile("cp.async.wait_group 0;" ::: "memory");
        __syncthreads();
    }

    // ---- epilogue: d = sqrt(max(sq1+sq2-2dot,0)) | 1e7; fused argmins ----
    int   m1v[8], m2v[8];
    float sq1v[8], sq2v[8];
#pragma unroll
    for (int mf = 0; mf < 4; mf++)
#pragma unroll
        for (int h = 0; h < 2; h++) {
            int rl = warp_m * 64 + mf * 16 + (lane >> 2) + 8 * h;
            m1v[mf * 2 + h]  = mask1[bt * HW + it * 128 + rl];
            sq1v[mf * 2 + h] = g_sq1[bt * HW + it * 128 + rl];
        }
#pragma unroll
    for (int nf = 0; nf < 4; nf++)
#pragma unroll
        for (int h = 0; h < 2; h++) {
            int cl = warp_n * 32 + nf * 8 + (lane & 3) * 2 + h;
            m2v[nf * 2 + h]  = mask2[bt * HW + jt * 128 + cl];
            sq2v[nf * 2 + h] = g_sq2[bt * HW + jt * 128 + cl];
        }

    unsigned long long rowbest[8], colbest[8];
#pragma unroll
    for (int q = 0; q < 8; q++) { rowbest[q] = ~0ULL; colbest[q] = ~0ULL; }

#pragma unroll
    for (int mf = 0; mf < 4; mf++)
#pragma unroll
        for (int nf = 0; nf < 4; nf++)
#pragma unroll
            for (int v = 0; v < 4; v++) {
                int ri = mf * 2 + (v >> 1);
                int ci = nf * 2 + (v & 1);
                int rl = warp_m * 64 + mf * 16 + (lane >> 2) + 8 * (v >> 1);
                int cl = warp_n * 32 + nf * 8 + (lane & 3) * 2 + (v & 1);
                float dot = acc[mf][nf][v];
                bool ok = (m1v[ri] > 0) && (m2v[ci] > 0);
                float d = ok ? sqrtf(fmaxf(sq1v[ri] + sq2v[ci] - 2.f * dot, 0.f)) : 1.0e7f;
                unsigned long long hb = ((unsigned long long)__float_as_uint(d) << 32);
                unsigned long long kr = hb | (unsigned)(jt * 128 + cl);
                unsigned long long kc = hb | (unsigned)(it * 128 + rl);
                rowbest[ri] = kr < rowbest[ri] ? kr : rowbest[ri];
                colbest[ci] = kc < colbest[ci] ? kc : colbest[ci];
            }

    // row reduce across quad (lanes sharing lane>>2)
#pragma unroll
    for (int q = 0; q < 8; q++) {
#pragma unroll
        for (int o = 1; o < 4; o <<= 1) {
            unsigned long long t = __shfl_xor_sync(0xFFFFFFFFu, rowbest[q], o);
            rowbest[q] = t < rowbest[q] ? t : rowbest[q];
        }
        if ((lane & 3) == 0) {
            int rl = warp_m * 64 + (q >> 1) * 16 + (lane >> 2) + 8 * (q & 1);
            atomicMin(&s_row[rl], rowbest[q]);
        }
    }
    // col reduce across lanes sharing lane&3
#pragma unroll
    for (int q = 0; q < 8; q++) {
#pragma unroll
        for (int o = 4; o < 32; o <<= 1) {
            unsigned long long t = __shfl_xor_sync(0xFFFFFFFFu, colbest[q], o);
            colbest[q] = t < colbest[q] ? t : colbest[q];
        }
        if ((lane >> 2) == 0) {
            int cl = warp_n * 32 + (q >> 1) * 8 + (lane & 3) * 2 + (q & 1);
            atomicMin(&s_col[cl], colbest[q]);
        }
    }
    __syncthreads();
    if (tid < 128) {
        atomicMin(&g_key1[bt * HW + it * 128 + tid], s_row[tid]);
        atomicMin(&g_key2[bt * HW + jt * 128 + tid], s_col[tid]);
    }
}

// ---------------- cyclic diff + stable top-128 (bitonic) --------------------
__global__ void topk_kernel(const int* __restrict__ mask1, const int* __restrict__ mask2,
                            const int* __restrict__ backup1, const int* __restrict__ backup2,
                            float* __restrict__ out) {
    int b   = blockIdx.x >> 1;
    int dir = blockIdx.x & 1;
    const unsigned long long* keyF  = dir ? g_key2 : g_key1;
    const unsigned long long* keyBk = dir ? g_key1 : g_key2;
    const int* mSrc   = dir ? mask2   : mask1;
    const int* mDst   = dir ? mask1   : mask2;
    const int* backup = dir ? backup2 : backup1;

    __shared__ unsigned long long keys[HW];
    __shared__ int s_cnt;
    int tid = threadIdx.x;
    if (tid == 0) s_cnt = 0;
    __syncthreads();

    int cnt = 0;
    for (int i = tid; i < HW; i += 512) {
        int srcm = mSrc[b * HW + i];
        cnt += (srcm > 0);
        int mf = (int)(keyF[b * HW + i] & 0xFFFFFFFFull);
        unsigned k32;
        if (srcm > 0 && mDst[b * HW + mf] > 0) {
            int cyc = (int)(keyBk[b * HW + mf] & 0xFFFFFFFFull);
            int dx = (cyc >> 6) - (i >> 6);
            int dy = (cyc & 63) - (i & 63);
            k32 = (unsigned)(dx * dx + dy * dy);
        } else {
            k32 = 0x7FFFFFFFu;
        }
        keys[i] = ((unsigned long long)k32 << 32) | (unsigned)i;
    }
#pragma unroll
    for (int o = 16; o; o >>= 1) cnt += __shfl_xor_sync(0xFFFFFFFFu, cnt, o);
    if ((tid & 31) == 0) atomicAdd(&s_cnt, cnt);
    __syncthreads();

    for (int kk = 2; kk <= HW; kk <<= 1)
        for (int jj = kk >> 1; jj > 0; jj >>= 1) {
            for (int i = tid; i < HW; i += 512) {
                int ixj = i ^ jj;
                if (ixj > i) {
                    unsigned long long a = keys[i], c = keys[ixj];
                    bool up = ((i & kk) == 0);
                    if ((a > c) == up) { keys[i] = c; keys[ixj] = a; }
                }
            }
            __syncthreads();
        }

    bool useTop = (s_cnt >= KSEL);
    if (tid < KSEL) {
        int idx   = useTop ? (int)(keys[tid] & 0xFFFFFFFFull) : backup[b * KSEL + tid];
        int match = (int)(keyF[b * HW + idx] & 0xFFFFFFFFull);
        int base  = dir * (BATCH * KSEL * 2) + b * (KSEL * 2) + tid * 2;
        out[base]     = (float)idx;
        out[base + 1] = (float)match;
    }
}

// ---------------- launch ----------------------------------------------------
extern "C" void kernel_launch(void* const* d_in, const int* in_sizes, int n_in,
                              void* d_out, int out_size) {
    const float* f1 = nullptr; const float* f2 = nullptr;
    const int* mask1 = nullptr; const int* mask2 = nullptr;
    const int* bk1 = nullptr; const int* bk2 = nullptr;
    for (int i = 0; i < n_in; i++) {
        long long sz = in_sizes[i];
        if (sz == FEAT_N || sz == (long long)FEAT_N * 4) {
            if (!f1) f1 = (const float*)d_in[i]; else f2 = (const float*)d_in[i];
        } else if (sz == MASK_N || sz == (long long)MASK_N * 4) {
            if (!mask1) mask1 = (const int*)d_in[i]; else mask2 = (const int*)d_in[i];
        } else if (sz == BK_N || sz == (long long)BK_N * 4) {
            if (!bk1) bk1 = (const int*)d_in[i]; else bk2 = (const int*)d_in[i];
        }
    }
    if (!f1 || !f2 || !mask1 || !mask2 || !bk1 || !bk2) {
        f1    = (const float*)d_in[0];
        f2    = (const float*)d_in[1];
        mask1 = (const int*)d_in[2];
        mask2 = (const int*)d_in[3];
        bk1   = (const int*)d_in[4];
        bk2   = (const int*)d_in[5];
    }
    float* out = (float*)d_out;

    cudaFuncSetAttribute(mma_argmin_kernel,
                         cudaFuncAttributeMaxDynamicSharedMemorySize, SMEM_DYN);

    init_keys_kernel<<<(MASK_N + 1023) / 1024, 1024>>>();
    normalize_kernel<<<MASK_N / 8, 256>>>(f1, mask1, 0);
    normalize_kernel<<<MASK_N / 8, 256>>>(f2, mask2, 1);
    dim3 grid(HW / 128, HW / 128, BATCH);
    mma_argmin_kernel<<<grid, 256, SMEM_DYN>>>(mask1, mask2);
    topk_kernel<<<BATCH * 2, 512>>>(mask1, mask2, bk1, bk2, out);
}

// round 10
// speedup vs baseline: 2.3643x; 1.0001x over previous
#include <cuda_runtime.h>
#include <cuda_fp16.h>
#include <stdint.h>

#define BATCH 8
#define HW    4096
#define CDIM  384
#define KSEL  128

#define FEAT_N (BATCH * HW * CDIM)   // 12582912
#define MASK_N (BATCH * HW)          // 32768
#define BK_N   (BATCH * KSEL)        // 1024

#define KC       32                  // k-chunk (halfs)
#define NCHUNK   (CDIM / KC)         // 12
#define STRH     40                  // smem row stride in halfs (80B, ldmatrix conflict-free)
#define TILE_HB  (128 * STRH * 2)    // 10240 bytes per 128x32 half tile
#define BUF_B    (4 * TILE_HB)       // a0,a1,b0,b1 = 40960 per stage
#define EPI_OFF  (2 * BUF_B)         // 81920
#define SMEM_DYN (EPI_OFF + 2048)    // + s_row/s_col (128 u64 each)

// ---------------- scratch (device globals: no allocations allowed) ----------
__device__ __half g_h0a[FEAT_N], g_h1a[FEAT_N];   // f1 = h0 + h1 (fp16 split)
__device__ __half g_h0b[FEAT_N], g_h1b[FEAT_N];   // f2 split
__device__ float g_sq1[MASK_N];
__device__ float g_sq2[MASK_N];
__device__ unsigned long long g_key1[MASK_N];  // argmin over j (match1)
__device__ unsigned long long g_key2[MASK_N];  // argmin over i (match2)

// ---------------- helpers ---------------------------------------------------
__device__ __forceinline__ uint32_t smem_u32(const void* p) {
    uint32_t a;
    asm("{ .reg .u64 t; cvta.to.shared.u64 t, %1; cvt.u32.u64 %0, t; }" : "=r"(a) : "l"(p));
    return a;
}
__device__ __forceinline__ void cp_async16(uint32_t dst, const void* src) {
    asm volatile("cp.async.cg.shared.global [%0], [%1], 16;" :: "r"(dst), "l"(src) : "memory");
}
__device__ __forceinline__ void ldsm4(uint32_t* r, uint32_t a) {
    asm volatile("ldmatrix.sync.aligned.m8n8.x4.shared.b16 {%0,%1,%2,%3}, [%4];"
                 : "=r"(r[0]), "=r"(r[1]), "=r"(r[2]), "=r"(r[3]) : "r"(a));
}
__device__ __forceinline__ void mma16816(float* c, const uint32_t* a, uint32_t b0, uint32_t b1) {
    asm volatile(
        "mma.sync.aligned.m16n8k16.row.col.f32.f16.f16.f32 "
        "{%0,%1,%2,%3}, {%4,%5,%6,%7}, {%8,%9}, {%0,%1,%2,%3};"
        : "+f"(c[0]), "+f"(c[1]), "+f"(c[2]), "+f"(c[3])
        : "r"(a[0]), "r"(a[1]), "r"(a[2]), "r"(a[3]), "r"(b0), "r"(b1));
}

// ---------------- init ------------------------------------------------------
__global__ void init_keys_kernel() {
    int t = blockIdx.x * blockDim.x + threadIdx.x;
    if (t < MASK_N) { g_key1[t] = ~0ULL; g_key2[t] = ~0ULL; }
}

// ------------- normalize + fp16 2-way split + sum(y^2) ----------------------
__global__ void normalize_kernel(const float* __restrict__ f,
                                 const int* __restrict__ mask, int which) {
    int token = blockIdx.x * 8 + (threadIdx.x >> 5);
    int lane  = threadIdx.x & 31;
    if (token >= MASK_N) return;
    const float* src = f + (size_t)token * CDIM;
    float v[12];
    float s = 0.f;
#pragma unroll
    for (int q = 0; q < 12; q++) { v[q] = src[lane + 32 * q]; s += v[q] * v[q]; }
#pragma unroll
    for (int o = 16; o; o >>= 1) s += __shfl_xor_sync(0xFFFFFFFFu, s, o);
    float norm = sqrtf(s);
    float m = (mask[token] > 0) ? 1.f : 0.f;
    __half* d0 = (which ? g_h0b : g_h0a) + (size_t)token * CDIM;
    __half* d1 = (which ? g_h1b : g_h1a) + (size_t)token * CDIM;
    float sq = 0.f;
#pragma unroll
    for (int q = 0; q < 12; q++) {
        float y = m * (v[q] / norm);
        sq += y * y;
        __half h0 = __float2half_rn(y);
        float  r  = y - __half2float(h0);
        __half h1 = __float2half_rn(r);
        d0[lane + 32 * q] = h0;
        d1[lane + 32 * q] = h1;
    }
#pragma unroll
    for (int o = 16; o; o >>= 1) sq += __shfl_xor_sync(0xFFFFFFFFu, sq, o);
    if (lane == 0) (which ? g_sq2 : g_sq1)[token] = sq;
}

// -------- mma.sync fp16x2-split GEMM (3 products) + fused argmin ------------
// CTA 128x128 tile, 256 threads = 8 warps (2 M x 4 N), warp tile 64x32.
// Inner k16 restructured into 3 product passes (a0b0, a0b1, a1b0) with ldsm
// interleaved between mma blocks; odd warps process kk in reverse order to
// break the post-barrier LDSM convoy.
__global__ void __launch_bounds__(256)
mma_argmin_kernel(const int* __restrict__ mask1, const int* __restrict__ mask2) {
    extern __shared__ char smem[];
    int bt = blockIdx.z, it = blockIdx.y, jt = blockIdx.x;
    int tid = threadIdx.x, wid = tid >> 5, lane = tid & 31;
    int warp_m = wid >> 2, warp_n = wid & 3;      // M: 2 x 64 rows, N: 4 x 32 cols

    uint32_t sbase = smem_u32(smem);
    unsigned long long* s_row = (unsigned long long*)(smem + EPI_OFF);
    unsigned long long* s_col = (unsigned long long*)(smem + EPI_OFF + 1024);
    if (tid < 128) { s_row[tid] = ~0ULL; s_col[tid] = ~0ULL; }

    size_t offA = ((size_t)bt * HW + it * 128) * CDIM;
    size_t offB = ((size_t)bt * HW + jt * 128) * CDIM;
    const __half* srcs[4] = { g_h0a + offA, g_h1a + offA, g_h0b + offB, g_h1b + offB };

    // cp.async fill: thread -> tile t = tid>>6, 8 segments of 16B
    int ft = tid >> 6, fs0 = tid & 63;
    const __half* fsrc = srcs[ft];
    uint32_t fdst0 = sbase + ft * TILE_HB;

    float acc[4][4][4];
#pragma unroll
    for (int mf = 0; mf < 4; mf++)
#pragma unroll
        for (int nf = 0; nf < 4; nf++)
#pragma unroll
            for (int v = 0; v < 4; v++) acc[mf][nf][v] = 0.f;

    // fill chunk 0 -> buffer 0
#pragma unroll
    for (int r = 0; r < 8; r++) {
        int s = fs0 + r * 64, row = s >> 2, seg = s & 3;
        cp_async16(fdst0 + row * 80 + seg * 16, fsrc + (size_t)row * CDIM + seg * 8);
    }
    asm volatile("cp.async.commit_group;" ::: "memory");
    asm volatile("cp.async.wait_group 0;" ::: "memory");
    __syncthreads();

    int lrow = lane & 15, lsel = (lane >> 4) << 3;   // ldmatrix lane addressing
    int kswap = wid & 1;                             // stagger: odd warps reverse kk

    for (int c = 0; c < NCHUNK; c++) {
        uint32_t buf = (uint32_t)(c & 1) * BUF_B;
        if (c < NCHUNK - 1) {
            uint32_t nbuf = (uint32_t)((c + 1) & 1) * BUF_B;
            int k0 = (c + 1) * KC;
#pragma unroll
            for (int r = 0; r < 8; r++) {
                int s = fs0 + r * 64, row = s >> 2, seg = s & 3;
                cp_async16(fdst0 + nbuf + row * 80 + seg * 16,
                           fsrc + (size_t)row * CDIM + k0 + seg * 8);
            }
            asm volatile("cp.async.commit_group;" ::: "memory");
        }
        uint32_t aBase  = sbase + buf;                      // split0 A
        uint32_t aBase1 = sbase + buf + TILE_HB;            // split1 A
        uint32_t bBase  = sbase + buf + 2 * TILE_HB;        // split0 B
        uint32_t bBase1 = sbase + buf + 3 * TILE_HB;        // split1 B
#pragma unroll
        for (int kk = 0; kk < 2; kk++) {
            int kb = ((kk ^ kswap) ? 16 : 0) + lsel;
            uint32_t arow = (uint32_t)(warp_m * 64 + lrow) * 80 + kb * 2;
            uint32_t brow = (uint32_t)(warp_n * 32 + lrow) * 80 + kb * 2;

            uint32_t a0[4][4], b0[2][4];
            // --- pass 0: a0 x b0 ---
#pragma unroll
            for (int mf = 0; mf < 4; mf++) ldsm4(a0[mf], aBase + arow + (uint32_t)(mf * 16) * 80);
#pragma unroll
            for (int ng = 0; ng < 2; ng++) ldsm4(b0[ng], bBase + brow + (uint32_t)(ng * 16) * 80);
#pragma unroll
            for (int mf = 0; mf < 4; mf++)
#pragma unroll
                for (int nf = 0; nf < 4; nf++) {
                    int ng = nf >> 1, hh = nf & 1;
                    mma16816(acc[mf][nf], a0[mf], b0[ng][hh], b0[ng][hh + 2]);
                }
            // --- pass 1: a0 x b1 ---
            {
                uint32_t b1[2][4];
#pragma unroll
                for (int ng = 0; ng < 2; ng++) ldsm4(b1[ng], bBase1 + brow + (uint32_t)(ng * 16) * 80);
#pragma unroll
                for (int mf = 0; mf < 4; mf++)
#pragma unroll
                    for (int nf = 0; nf < 4; nf++) {
                        int ng = nf >> 1, hh = nf & 1;
                        mma16816(acc[mf][nf], a0[mf], b1[ng][hh], b1[ng][hh + 2]);
                    }
            }
            // --- pass 2: a1 x b0 (a0 dead; regs reusable for next kk) ---
            {
                uint32_t a1[4][4];
#pragma unroll
                for (int mf = 0; mf < 4; mf++) ldsm4(a1[mf], aBase1 + arow + (uint32_t)(mf * 16) * 80);
#pragma unroll
                for (int mf = 0; mf < 4; mf++)
#pragma unroll
                    for (int nf = 0; nf < 4; nf++) {
                        int ng = nf >> 1, hh = nf & 1;
                        mma16816(acc[mf][nf], a1[mf], b0[ng][hh], b0[ng][hh + 2]);
                    }
            }
        }
        asm volatile("cp.async.wait_group 0;" ::: "memory");
        __syncthreads();
    }

    // ---- epilogue: d = sqrt(max(sq1+sq2-2dot,0)) | 1e7; fused argmins ----
    int   m1v[8], m2v[8];
    float sq1v[8], sq2v[8];
#pragma unroll
    for (int mf = 0; mf < 4; mf++)
#pragma unroll
        for (int h = 0; h < 2; h++) {
            int rl = warp_m * 64 + mf * 16 + (lane >> 2) + 8 * h;
            m1v[mf * 2 + h]  = mask1[bt * HW + it * 128 + rl];
            sq1v[mf * 2 + h] = g_sq1[bt * HW + it * 128 + rl];
        }
#pragma unroll
    for (int nf = 0; nf < 4; nf++)
#pragma unroll
        for (int h = 0; h < 2; h++) {
            int cl = warp_n * 32 + nf * 8 + (lane & 3) * 2 + h;
            m2v[nf * 2 + h]  = mask2[bt * HW + jt * 128 + cl];
            sq2v[nf * 2 + h] = g_sq2[bt * HW + jt * 128 + cl];
        }

    unsigned long long rowbest[8], colbest[8];
#pragma unroll
    for (int q = 0; q < 8; q++) { rowbest[q] = ~0ULL; colbest[q] = ~0ULL; }

#pragma unroll
    for (int mf = 0; mf < 4; mf++)
#pragma unroll
        for (int nf = 0; nf < 4; nf++)
#pragma unroll
            for (int v = 0; v < 4; v++) {
                int ri = mf * 2 + (v >> 1);
                int ci = nf * 2 + (v & 1);
                int rl = warp_m * 64 + mf * 16 + (lane >> 2) + 8 * (v >> 1);
                int cl = warp_n * 32 + nf * 8 + (lane & 3) * 2 + (v & 1);
                float dot = acc[mf][nf][v];
                bool ok = (m1v[ri] > 0) && (m2v[ci] > 0);
                float d = ok ? sqrtf(fmaxf(sq1v[ri] + sq2v[ci] - 2.f * dot, 0.f)) : 1.0e7f;
                unsigned long long hb = ((unsigned long long)__float_as_uint(d) << 32);
                unsigned long long kr = hb | (unsigned)(jt * 128 + cl);
                unsigned long long kc = hb | (unsigned)(it * 128 + rl);
                rowbest[ri] = kr < rowbest[ri] ? kr : rowbest[ri];
                colbest[ci] = kc < colbest[ci] ? kc : colbest[ci];
            }

    // row reduce across quad (lanes sharing lane>>2)
#pragma unroll
    for (int q = 0; q < 8; q++) {
#pragma unroll
        for (int o = 1; o < 4; o <<= 1) {
            unsigned long long t = __shfl_xor_sync(0xFFFFFFFFu, rowbest[q], o);
            rowbest[q] = t < rowbest[q] ? t : rowbest[q];
        }
        if ((lane & 3) == 0) {
            int rl = warp_m * 64 + (q >> 1) * 16 + (lane >> 2) + 8 * (q & 1);
            atomicMin(&s_row[rl], rowbest[q]);
        }
    }
    // col reduce across lanes sharing lane&3
#pragma unroll
    for (int q = 0; q < 8; q++) {
#pragma unroll
        for (int o = 4; o < 32; o <<= 1) {
            unsigned long long t = __shfl_xor_sync(0xFFFFFFFFu, colbest[q], o);
            colbest[q] = t < colbest[q] ? t : colbest[q];
        }
        if ((lane >> 2) == 0) {
            int cl = warp_n * 32 + (q >> 1) * 8 + (lane & 3) * 2 + (q & 1);
            atomicMin(&s_col[cl], colbest[q]);
        }
    }
    __syncthreads();
    if (tid < 128) {
        atomicMin(&g_key1[bt * HW + it * 128 + tid], s_row[tid]);
        atomicMin(&g_key2[bt * HW + jt * 128 + tid], s_col[tid]);
    }
}

// ---------------- cyclic diff + stable top-128 (bitonic) --------------------
__global__ void topk_kernel(const int* __restrict__ mask1, const int* __restrict__ mask2,
                            const int* __restrict__ backup1, const int* __restrict__ backup2,
                            float* __restrict__ out) {
    int b   = blockIdx.x >> 1;
    int dir = blockIdx.x & 1;
    const unsigned long long* keyF  = dir ? g_key2 : g_key1;
    const unsigned long long* keyBk = dir ? g_key1 : g_key2;
    const int* mSrc   = dir ? mask2   : mask1;
    const int* mDst   = dir ? mask1   : mask2;
    const int* backup = dir ? backup2 : backup1;

    __shared__ unsigned long long keys[HW];
    __shared__ int s_cnt;
    int tid = threadIdx.x;
    if (tid == 0) s_cnt = 0;
    __syncthreads();

    int cnt = 0;
    for (int i = tid; i < HW; i += 512) {
        int srcm = mSrc[b * HW + i];
        cnt += (srcm > 0);
        int mf = (int)(keyF[b * HW + i] & 0xFFFFFFFFull);
        unsigned k32;
        if (srcm > 0 && mDst[b * HW + mf] > 0) {
            int cyc = (int)(keyBk[b * HW + mf] & 0xFFFFFFFFull);
            int dx = (cyc >> 6) - (i >> 6);
            int dy = (cyc & 63) - (i & 63);
            k32 = (unsigned)(dx * dx + dy * dy);
        } else {
            k32 = 0x7FFFFFFFu;
        }
        keys[i] = ((unsigned long long)k32 << 32) | (unsigned)i;
    }
#pragma unroll
    for (int o = 16; o; o >>= 1) cnt += __shfl_xor_sync(0xFFFFFFFFu, cnt, o);
    if ((tid & 31) == 0) atomicAdd(&s_cnt, cnt);
    __syncthreads();

    for (int kk = 2; kk <= HW; kk <<= 1)
        for (int jj = kk >> 1; jj > 0; jj >>= 1) {
            for (int i = tid; i < HW; i += 512) {
                int ixj = i ^ jj;
                if (ixj > i) {
                    unsigned long long a = keys[i], c = keys[ixj];
                    bool up = ((i & kk) == 0);
                    if ((a > c) == up) { keys[i] = c; keys[ixj] = a; }
                }
            }
            __syncthreads();
        }

    bool useTop = (s_cnt >= KSEL);
    if (tid < KSEL) {
        int idx   = useTop ? (int)(keys[tid] & 0xFFFFFFFFull) : backup[b * KSEL + tid];
        int match = (int)(keyF[b * HW + idx] & 0xFFFFFFFFull);
        int base  = dir * (BATCH * KSEL * 2) + b * (KSEL * 2) + tid * 2;
        out[base]     = (float)idx;
        out[base + 1] = (float)match;
    }
}

// ---------------- launch ----------------------------------------------------
extern "C" void kernel_launch(void* const* d_in, const int* in_sizes, int n_in,
                              void* d_out, int out_size) {
    const float* f1 = nullptr; const float* f2 = nullptr;
    const int* mask1 = nullptr; const int* mask2 = nullptr;
    const int* bk1 = nullptr; const int* bk2 = nullptr;
    for (int i = 0; i < n_in; i++) {
        long long sz = in_sizes[i];
        if (sz == FEAT_N || sz == (long long)FEAT_N * 4) {
            if (!f1) f1 = (const float*)d_in[i]; else f2 = (const float*)d_in[i];
        } else if (sz == MASK_N || sz == (long long)MASK_N * 4) {
            if (!mask1) mask1 = (const int*)d_in[i]; else mask2 = (const int*)d_in[i];
        } else if (sz == BK_N || sz == (long long)BK_N * 4) {
            if (!bk1) bk1 = (const int*)d_in[i]; else bk2 = (const int*)d_in[i];
        }
    }
    if (!f1 || !f2 || !mask1 || !mask2 || !bk1 || !bk2) {
        f1    = (const float*)d_in[0];
        f2    = (const float*)d_in[1];
        mask1 = (const int*)d_in[2];
        mask2 = (const int*)d_in[3];
        bk1   = (const int*)d_in[4];
        bk2   = (const int*)d_in[5];
    }
    float* out = (float*)d_out;

    cudaFuncSetAttribute(mma_argmin_kernel,
                         cudaFuncAttributeMaxDynamicSharedMemorySize, SMEM_DYN);

    init_keys_kernel<<<(MASK_N + 1023) / 1024, 1024>>>();
    normalize_kernel<<<MASK_N / 8, 256>>>(f1, mask1, 0);
    normalize_kernel<<<MASK_N / 8, 256>>>(f2, mask2, 1);
    dim3 grid(HW / 128, HW / 128, BATCH);
    mma_argmin_kernel<<<grid, 256, SMEM_DYN>>>(mask1, mask2);
    topk_kernel<<<BATCH * 2, 512>>>(mask1, mask2, bk1, bk2, out);
}

// round 11
// speedup vs baseline: 2.3845x; 1.0085x over previous
#include <cuda_runtime.h>
#include <cuda_fp16.h>
#include <stdint.h>

#define BATCH 8
#define HW    4096
#define CDIM  384
#define KSEL  128

#define FEAT_N (BATCH * HW * CDIM)   // 12582912
#define MASK_N (BATCH * HW)          // 32768
#define BK_N   (BATCH * KSEL)        // 1024

#define KC       32                  // k-chunk (halfs)
#define NCHUNK   (CDIM / KC)         // 12
#define STRH     40                  // smem row stride in halfs (80B, ldmatrix conflict-free)
#define TILE_HB  (128 * STRH * 2)    // 10240 bytes per 128x32 half tile
#define BUF_B    (4 * TILE_HB)       // a0,a1,b0,b1 = 40960 per stage
#define EPI_OFF  (2 * BUF_B)         // 81920
#define SMEM_DYN (EPI_OFF + 2048)    // + s_row/s_col (128 u64 each)

// ---------------- scratch (device globals: no allocations allowed) ----------
__device__ __half g_h0a[FEAT_N], g_h1a[FEAT_N];   // f1 = h0 + h1 (fp16 split)
__device__ __half g_h0b[FEAT_N], g_h1b[FEAT_N];   // f2 split
__device__ float g_sq1[MASK_N];
__device__ float g_sq2[MASK_N];
__device__ unsigned long long g_key1[MASK_N];  // argmin over j (match1)
__device__ unsigned long long g_key2[MASK_N];  // argmin over i (match2)

// ---------------- helpers ---------------------------------------------------
__device__ __forceinline__ uint32_t smem_u32(const void* p) {
    uint32_t a;
    asm("{ .reg .u64 t; cvta.to.shared.u64 t, %1; cvt.u32.u64 %0, t; }" : "=r"(a) : "l"(p));
    return a;
}
__device__ __forceinline__ void cp_async16(uint32_t dst, const void* src) {
    asm volatile("cp.async.cg.shared.global [%0], [%1], 16;" :: "r"(dst), "l"(src) : "memory");
}
__device__ __forceinline__ void ldsm4(uint32_t* r, uint32_t a) {
    asm volatile("ldmatrix.sync.aligned.m8n8.x4.shared.b16 {%0,%1,%2,%3}, [%4];"
                 : "=r"(r[0]), "=r"(r[1]), "=r"(r[2]), "=r"(r[3]) : "r"(a));
}
__device__ __forceinline__ void mma16816(float* c, const uint32_t* a, uint32_t b0, uint32_t b1) {
    asm volatile(
        "mma.sync.aligned.m16n8k16.row.col.f32.f16.f16.f32 "
        "{%0,%1,%2,%3}, {%4,%5,%6,%7}, {%8,%9}, {%0,%1,%2,%3};"
        : "+f"(c[0]), "+f"(c[1]), "+f"(c[2]), "+f"(c[3])
        : "r"(a[0]), "r"(a[1]), "r"(a[2]), "r"(a[3]), "r"(b0), "r"(b1));
}

// ------------- normalize + fp16 2-way split + sum(y^2) + key init ----------
__global__ void normalize_kernel(const float* __restrict__ f,
                                 const int* __restrict__ mask, int which) {
    int token = blockIdx.x * 8 + (threadIdx.x >> 5);
    int lane  = threadIdx.x & 31;
    if (token >= MASK_N) return;
    const float* src = f + (size_t)token * CDIM;
    float v[12];
    float s = 0.f;
#pragma unroll
    for (int q = 0; q < 12; q++) { v[q] = src[lane + 32 * q]; s += v[q] * v[q]; }
#pragma unroll
    for (int o = 16; o; o >>= 1) s += __shfl_xor_sync(0xFFFFFFFFu, s, o);
    float norm = sqrtf(s);
    float m = (mask[token] > 0) ? 1.f : 0.f;
    __half* d0 = (which ? g_h0b : g_h0a) + (size_t)token * CDIM;
    __half* d1 = (which ? g_h1b : g_h1a) + (size_t)token * CDIM;
    float sq = 0.f;
#pragma unroll
    for (int q = 0; q < 12; q++) {
        float y = m * (v[q] / norm);
        sq += y * y;
        __half h0 = __float2half_rn(y);
        float  r  = y - __half2float(h0);
        __half h1 = __float2half_rn(r);
        d0[lane + 32 * q] = h0;
        d1[lane + 32 * q] = h1;
    }
#pragma unroll
    for (int o = 16; o; o >>= 1) sq += __shfl_xor_sync(0xFFFFFFFFu, sq, o);
    if (lane == 0) {
        (which ? g_sq2 : g_sq1)[token] = sq;
        (which ? g_key2 : g_key1)[token] = ~0ULL;   // fused key init
    }
}

// -------- mma.sync fp16x2-split GEMM (3 products) + fused argmin ------------
// CTA 128x128 tile, 256 threads = 8 warps (2 M x 4 N), warp tile 64x32.
// Software-pipelined fragment buffers: each pass's ldsm issues during the
// previous pass's mma block. Anti-phase: warp_m groups process k16 halves in
// opposite order (SMSP i holds wid i and i+4 -> opposite phases).
__global__ void __launch_bounds__(256)
mma_argmin_kernel(const int* __restrict__ mask1, const int* __restrict__ mask2) {
    extern __shared__ char smem[];
    int bt = blockIdx.z, it = blockIdx.y, jt = blockIdx.x;
    int tid = threadIdx.x, wid = tid >> 5, lane = tid & 31;
    int warp_m = wid >> 2, warp_n = wid & 3;      // M: 2 x 64 rows, N: 4 x 32 cols

    uint32_t sbase = smem_u32(smem);
    unsigned long long* s_row = (unsigned long long*)(smem + EPI_OFF);
    unsigned long long* s_col = (unsigned long long*)(smem + EPI_OFF + 1024);
    if (tid < 128) { s_row[tid] = ~0ULL; s_col[tid] = ~0ULL; }

    size_t offA = ((size_t)bt * HW + it * 128) * CDIM;
    size_t offB = ((size_t)bt * HW + jt * 128) * CDIM;
    const __half* srcs[4] = { g_h0a + offA, g_h1a + offA, g_h0b + offB, g_h1b + offB };

    // cp.async fill: thread -> tile t = tid>>6, 8 segments of 16B
    int ft = tid >> 6, fs0 = tid & 63;
    const __half* fsrc = srcs[ft];
    uint32_t fdst0 = sbase + ft * TILE_HB;

    float acc[4][4][4];
#pragma unroll
    for (int mf = 0; mf < 4; mf++)
#pragma unroll
        for (int nf = 0; nf < 4; nf++)
#pragma unroll
            for (int v = 0; v < 4; v++) acc[mf][nf][v] = 0.f;

    // fill chunk 0 -> buffer 0
#pragma unroll
    for (int r = 0; r < 8; r++) {
        int s = fs0 + r * 64, row = s >> 2, seg = s & 3;
        cp_async16(fdst0 + row * 80 + seg * 16, fsrc + (size_t)row * CDIM + seg * 8);
    }
    asm volatile("cp.async.commit_group;" ::: "memory");
    asm volatile("cp.async.wait_group 0;" ::: "memory");
    __syncthreads();

    int lrow = lane & 15, lsel = (lane >> 4) << 3;   // ldmatrix lane addressing
    int kswap = warp_m;                              // TRUE anti-phase within SMSP

    for (int c = 0; c < NCHUNK; c++) {
        uint32_t buf = (uint32_t)(c & 1) * BUF_B;
        if (c < NCHUNK - 1) {
            uint32_t nbuf = (uint32_t)((c + 1) & 1) * BUF_B;
            int k0g = (c + 1) * KC;
#pragma unroll
            for (int r = 0; r < 8; r++) {
                int s = fs0 + r * 64, row = s >> 2, seg = s & 3;
                cp_async16(fdst0 + nbuf + row * 80 + seg * 16,
                           fsrc + (size_t)row * CDIM + k0g + seg * 8);
            }
            asm volatile("cp.async.commit_group;" ::: "memory");
        }
        // k-offsets (in halfs, incl. lane select); warp_m groups opposite order
        uint32_t k0 = (uint32_t)(lsel + (kswap ? 16 : 0)) * 2;
        uint32_t k1 = (uint32_t)(lsel + (kswap ? 0 : 16)) * 2;
        uint32_t aRow = (uint32_t)(warp_m * 64 + lrow) * 80;
        uint32_t bRow = (uint32_t)(warp_n * 32 + lrow) * 80;
        uint32_t a0Base = sbase + buf + aRow;                 // A split0
        uint32_t a1Base = sbase + buf + TILE_HB + aRow;       // A split1
        uint32_t b0Base = sbase + buf + 2 * TILE_HB + bRow;   // B split0
        uint32_t b1Base = sbase + buf + 3 * TILE_HB + bRow;   // B split1

        uint32_t A0[4][4], A1[4][4], B0[2][4], B1[2][4];
        // prologue: A0 <- a0[k0], B0 <- b0[k0]
#pragma unroll
        for (int mf = 0; mf < 4; mf++) ldsm4(A0[mf], a0Base + k0 + (uint32_t)(mf * 16) * 80);
#pragma unroll
        for (int ng = 0; ng < 2; ng++) ldsm4(B0[ng], b0Base + k0 + (uint32_t)(ng * 16) * 80);

        // S0: ld B1<-b1[k0]; mma a0[k0] x b0[k0]
#pragma unroll
        for (int ng = 0; ng < 2; ng++) ldsm4(B1[ng], b1Base + k0 + (uint32_t)(ng * 16) * 80);
#pragma unroll
        for (int mf = 0; mf < 4; mf++)
#pragma unroll
            for (int nf = 0; nf < 4; nf++)
                mma16816(acc[mf][nf], A0[mf], B0[nf >> 1][nf & 1], B0[nf >> 1][(nf & 1) + 2]);

        // S1: ld A1<-a1[k0]; mma a0[k0] x b1[k0]
#pragma unroll
        for (int mf = 0; mf < 4; mf++) ldsm4(A1[mf], a1Base + k0 + (uint32_t)(mf * 16) * 80);
#pragma unroll
        for (int mf = 0; mf < 4; mf++)
#pragma unroll
            for (int nf = 0; nf < 4; nf++)
                mma16816(acc[mf][nf], A0[mf], B1[nf >> 1][nf & 1], B1[nf >> 1][(nf & 1) + 2]);

        // S2: ld A0<-a0[k1], B1<-b0[k1]; mma a1[k0] x b0[k0]
#pragma unroll
        for (int mf = 0; mf < 4; mf++) ldsm4(A0[mf], a0Base + k1 + (uint32_t)(mf * 16) * 80);
#pragma unroll
        for (int ng = 0; ng < 2; ng++) ldsm4(B1[ng], b0Base + k1 + (uint32_t)(ng * 16) * 80);
#pragma unroll
        for (int mf = 0; mf < 4; mf++)
#pragma unroll
            for (int nf = 0; nf < 4; nf++)
                mma16816(acc[mf][nf], A1[mf], B0[nf >> 1][nf & 1], B0[nf >> 1][(nf & 1) + 2]);

        // S3: ld B0<-b1[k1]; mma a0[k1] x b0[k1]
#pragma unroll
        for (int ng = 0; ng < 2; ng++) ldsm4(B0[ng], b1Base + k1 + (uint32_t)(ng * 16) * 80);
#pragma unroll
        for (int mf = 0; mf < 4; mf++)
#pragma unroll
            for (int nf = 0; nf < 4; nf++)
                mma16816(acc[mf][nf], A0[mf], B1[nf >> 1][nf & 1], B1[nf >> 1][(nf & 1) + 2]);

        // S4: ld A1<-a1[k1]; mma a0[k1] x b1[k1]
#pragma unroll
        for (int mf = 0; mf < 4; mf++) ldsm4(A1[mf], a1Base + k1 + (uint32_t)(mf * 16) * 80);
#pragma unroll
        for (int mf = 0; mf < 4; mf++)
#pragma unroll
            for (int nf = 0; nf < 4; nf++)
                mma16816(acc[mf][nf], A0[mf], B0[nf >> 1][nf & 1], B0[nf >> 1][(nf & 1) + 2]);

        // S5: mma a1[k1] x b0[k1]
#pragma unroll
        for (int mf = 0; mf < 4; mf++)
#pragma unroll
            for (int nf = 0; nf < 4; nf++)
                mma16816(acc[mf][nf], A1[mf], B1[nf >> 1][nf & 1], B1[nf >> 1][(nf & 1) + 2]);

        asm volatile("cp.async.wait_group 0;" ::: "memory");
        __syncthreads();
    }

    // ---- epilogue: d = sqrt(max(sq1+sq2-2dot,0)) | 1e7; fused argmins ----
    int   m1v[8], m2v[8];
    float sq1v[8], sq2v[8];
#pragma unroll
    for (int mf = 0; mf < 4; mf++)
#pragma unroll
        for (int h = 0; h < 2; h++) {
            int rl = warp_m * 64 + mf * 16 + (lane >> 2) + 8 * h;
            m1v[mf * 2 + h]  = mask1[bt * HW + it * 128 + rl];
            sq1v[mf * 2 + h] = g_sq1[bt * HW + it * 128 + rl];
        }
#pragma unroll
    for (int nf = 0; nf < 4; nf++)
#pragma unroll
        for (int h = 0; h < 2; h++) {
            int cl = warp_n * 32 + nf * 8 + (lane & 3) * 2 + h;
            m2v[nf * 2 + h]  = mask2[bt * HW + jt * 128 + cl];
            sq2v[nf * 2 + h] = g_sq2[bt * HW + jt * 128 + cl];
        }

    unsigned long long rowbest[8], colbest[8];
#pragma unroll
    for (int q = 0; q < 8; q++) { rowbest[q] = ~0ULL; colbest[q] = ~0ULL; }

#pragma unroll
    for (int mf = 0; mf < 4; mf++)
#pragma unroll
        for (int nf = 0; nf < 4; nf++)
#pragma unroll
            for (int v = 0; v < 4; v++) {
                int ri = mf * 2 + (v >> 1);
                int ci = nf * 2 + (v & 1);
                int rl = warp_m * 64 + mf * 16 + (lane >> 2) + 8 * (v >> 1);
                int cl = warp_n * 32 + nf * 8 + (lane & 3) * 2 + (v & 1);
                float dot = acc[mf][nf][v];
                bool ok = (m1v[ri] > 0) && (m2v[ci] > 0);
                float d = ok ? sqrtf(fmaxf(sq1v[ri] + sq2v[ci] - 2.f * dot, 0.f)) : 1.0e7f;
                unsigned long long hb = ((unsigned long long)__float_as_uint(d) << 32);
                unsigned long long kr = hb | (unsigned)(jt * 128 + cl);
                unsigned long long kc = hb | (unsigned)(it * 128 + rl);
                rowbest[ri] = kr < rowbest[ri] ? kr : rowbest[ri];
                colbest[ci] = kc < colbest[ci] ? kc : colbest[ci];
            }

    // row reduce across quad (lanes sharing lane>>2)
#pragma unroll
    for (int q = 0; q < 8; q++) {
#pragma unroll
        for (int o = 1; o < 4; o <<= 1) {
            unsigned long long t = __shfl_xor_sync(0xFFFFFFFFu, rowbest[q], o);
            rowbest[q] = t < rowbest[q] ? t : rowbest[q];
        }
        if ((lane & 3) == 0) {
            int rl = warp_m * 64 + (q >> 1) * 16 + (lane >> 2) + 8 * (q & 1);
            atomicMin(&s_row[rl], rowbest[q]);
        }
    }
    // col reduce across lanes sharing lane&3
#pragma unroll
    for (int q = 0; q < 8; q++) {
#pragma unroll
        for (int o = 4; o < 32; o <<= 1) {
            unsigned long long t = __shfl_xor_sync(0xFFFFFFFFu, colbest[q], o);
            colbest[q] = t < colbest[q] ? t : colbest[q];
        }
        if ((lane >> 2) == 0) {
            int cl = warp_n * 32 + (q >> 1) * 8 + (lane & 3) * 2 + (q & 1);
            atomicMin(&s_col[cl], colbest[q]);
        }
    }
    __syncthreads();
    if (tid < 128) {
        atomicMin(&g_key1[bt * HW + it * 128 + tid], s_row[tid]);
        atomicMin(&g_key2[bt * HW + jt * 128 + tid], s_col[tid]);
    }
}

// ---------------- cyclic diff + stable top-128 (bitonic) --------------------
__global__ void topk_kernel(const int* __restrict__ mask1, const int* __restrict__ mask2,
                            const int* __restrict__ backup1, const int* __restrict__ backup2,
                            float* __restrict__ out) {
    int b   = blockIdx.x >> 1;
    int dir = blockIdx.x & 1;
    const unsigned long long* keyF  = dir ? g_key2 : g_key1;
    const unsigned long long* keyBk = dir ? g_key1 : g_key2;
    const int* mSrc   = dir ? mask2   : mask1;
    const int* mDst   = dir ? mask1   : mask2;
    const int* backup = dir ? backup2 : backup1;

    __shared__ unsigned long long keys[HW];
    __shared__ int s_cnt;
    int tid = threadIdx.x;
    if (tid == 0) s_cnt = 0;
    __syncthreads();

    int cnt = 0;
    for (int i = tid; i < HW; i += 512) {
        int srcm = mSrc[b * HW + i];
        cnt += (srcm > 0);
        int mf = (int)(keyF[b * HW + i] & 0xFFFFFFFFull);
        unsigned k32;
        if (srcm > 0 && mDst[b * HW + mf] > 0) {
            int cyc = (int)(keyBk[b * HW + mf] & 0xFFFFFFFFull);
            int dx = (cyc >> 6) - (i >> 6);
            int dy = (cyc & 63) - (i & 63);
            k32 = (unsigned)(dx * dx + dy * dy);
        } else {
            k32 = 0x7FFFFFFFu;
        }
        keys[i] = ((unsigned long long)k32 << 32) | (unsigned)i;
    }
#pragma unroll
    for (int o = 16; o; o >>= 1) cnt += __shfl_xor_sync(0xFFFFFFFFu, cnt, o);
    if ((tid & 31) == 0) atomicAdd(&s_cnt, cnt);
    __syncthreads();

    for (int kk = 2; kk <= HW; kk <<= 1)
        for (int jj = kk >> 1; jj > 0; jj >>= 1) {
            for (int i = tid; i < HW; i += 512) {
                int ixj = i ^ jj;
                if (ixj > i) {
                    unsigned long long a = keys[i], c = keys[ixj];
                    bool up = ((i & kk) == 0);
                    if ((a > c) == up) { keys[i] = c; keys[ixj] = a; }
                }
            }
            __syncthreads();
        }

    bool useTop = (s_cnt >= KSEL);
    if (tid < KSEL) {
        int idx   = useTop ? (int)(keys[tid] & 0xFFFFFFFFull) : backup[b * KSEL + tid];
        int match = (int)(keyF[b * HW + idx] & 0xFFFFFFFFull);
        int base  = dir * (BATCH * KSEL * 2) + b * (KSEL * 2) + tid * 2;
        out[base]     = (float)idx;
        out[base + 1] = (float)match;
    }
}

// ---------------- launch ----------------------------------------------------
extern "C" void kernel_launch(void* const* d_in, const int* in_sizes, int n_in,
                              void* d_out, int out_size) {
    const float* f1 = nullptr; const float* f2 = nullptr;
    const int* mask1 = nullptr; const int* mask2 = nullptr;
    const int* bk1 = nullptr; const int* bk2 = nullptr;
    for (int i = 0; i < n_in; i++) {
        long long sz = in_sizes[i];
        if (sz == FEAT_N || sz == (long long)FEAT_N * 4) {
            if (!f1) f1 = (const float*)d_in[i]; else f2 = (const float*)d_in[i];
        } else if (sz == MASK_N || sz == (long long)MASK_N * 4) {
            if (!mask1) mask1 = (const int*)d_in[i]; else mask2 = (const int*)d_in[i];
        } else if (sz == BK_N || sz == (long long)BK_N * 4) {
            if (!bk1) bk1 = (const int*)d_in[i]; else bk2 = (const int*)d_in[i];
        }
    }
    if (!f1 || !f2 || !mask1 || !mask2 || !bk1 || !bk2) {
        f1    = (const float*)d_in[0];
        f2    = (const float*)d_in[1];
        mask1 = (const int*)d_in[2];
        mask2 = (const int*)d_in[3];
        bk1   = (const int*)d_in[4];
        bk2   = (const int*)d_in[5];
    }
    float* out = (float*)d_out;

    cudaFuncSetAttribute(mma_argmin_kernel,
                         cudaFuncAttributeMaxDynamicSharedMemorySize, SMEM_DYN);

    normalize_kernel<<<MASK_N / 8, 256>>>(f1, mask1, 0);
    normalize_kernel<<<MASK_N / 8, 256>>>(f2, mask2, 1);
    dim3 grid(HW / 128, HW / 128, BATCH);
    mma_argmin_kernel<<<grid, 256, SMEM_DYN>>>(mask1, mask2);
    topk_kernel<<<BATCH * 2, 512>>>(mask1, mask2, bk1, bk2, out);
}

// round 13
// speedup vs baseline: 2.4782x; 1.0393x over previous
#include <cuda_runtime.h>
#include <cuda_fp16.h>
#include <stdint.h>

#define BATCH 8
#define HW    4096
#define CDIM  384
#define KSEL  128

#define FEAT_N (BATCH * HW * CDIM)   // 12582912
#define MASK_N (BATCH * HW)          // 32768
#define BK_N   (BATCH * KSEL)        // 1024

#define KC       32                  // k-chunk (halfs)
#define NCHUNK   (CDIM / KC)         // 12
#define STRH     40                  // smem row stride in halfs (80B, ldmatrix conflict-free)
#define TILE_HB  (128 * STRH * 2)    // 10240 bytes per 128x32 half tile
#define BUF_B    (4 * TILE_HB)       // a0,a1,b0,b1 = 40960 per stage
#define EPI_OFF  (2 * BUF_B)         // 81920
#define SMEM_DYN (EPI_OFF + 2048)    // + s_row/s_col (128 u64 each)

// ---------------- scratch (device globals: no allocations allowed) ----------
__device__ __half g_h0a[FEAT_N], g_h1a[FEAT_N];   // f1 = h0 + h1 (fp16 split)
__device__ __half g_h0b[FEAT_N], g_h1b[FEAT_N];   // f2 split
__device__ float g_sq1[MASK_N];
__device__ float g_sq2[MASK_N];
__device__ unsigned long long g_key1[MASK_N];  // argmin over j (match1)
__device__ unsigned long long g_key2[MASK_N];  // argmin over i (match2)

// ---------------- helpers ---------------------------------------------------
__device__ __forceinline__ uint32_t smem_u32(const void* p) {
    uint32_t a;
    asm("{ .reg .u64 t; cvta.to.shared.u64 t, %1; cvt.u32.u64 %0, t; }" : "=r"(a) : "l"(p));
    return a;
}
__device__ __forceinline__ void cp_async16(uint32_t dst, const void* src) {
    asm volatile("cp.async.cg.shared.global [%0], [%1], 16;" :: "r"(dst), "l"(src) : "memory");
}
__device__ __forceinline__ void ldsm4(uint32_t* r, uint32_t a) {
    asm volatile("ldmatrix.sync.aligned.m8n8.x4.shared.b16 {%0,%1,%2,%3}, [%4];"
                 : "=r"(r[0]), "=r"(r[1]), "=r"(r[2]), "=r"(r[3]) : "r"(a));
}
__device__ __forceinline__ void mma16816(float* c, const uint32_t* a, uint32_t b0, uint32_t b1) {
    asm volatile(
        "mma.sync.aligned.m16n8k16.row.col.f32.f16.f16.f32 "
        "{%0,%1,%2,%3}, {%4,%5,%6,%7}, {%8,%9}, {%0,%1,%2,%3};"
        : "+f"(c[0]), "+f"(c[1]), "+f"(c[2]), "+f"(c[3])
        : "r"(a[0]), "r"(a[1]), "r"(a[2]), "r"(a[3]), "r"(b0), "r"(b1));
}

// ------ normalize both features (one launch) + fp16 split + sq + key init ---
__global__ void normalize_kernel(const float* __restrict__ fa, const float* __restrict__ fb,
                                 const int* __restrict__ ma, const int* __restrict__ mb) {
    int half = gridDim.x >> 1;
    int which = blockIdx.x >= half;
    int blk   = which ? blockIdx.x - half : blockIdx.x;
    const float* f    = which ? fb : fa;
    const int*   mask = which ? mb : ma;

    int token = blk * 8 + (threadIdx.x >> 5);
    int lane  = threadIdx.x & 31;
    if (token >= MASK_N) return;
    const float* src = f + (size_t)token * CDIM;
    float v[12];
    float s = 0.f;
#pragma unroll
    for (int q = 0; q < 12; q++) { v[q] = src[lane + 32 * q]; s += v[q] * v[q]; }
#pragma unroll
    for (int o = 16; o; o >>= 1) s += __shfl_xor_sync(0xFFFFFFFFu, s, o);
    float norm = sqrtf(s);
    float m = (mask[token] > 0) ? 1.f : 0.f;
    __half* d0 = (which ? g_h0b : g_h0a) + (size_t)token * CDIM;
    __half* d1 = (which ? g_h1b : g_h1a) + (size_t)token * CDIM;
    float sq = 0.f;
#pragma unroll
    for (int q = 0; q < 12; q++) {
        float y = m * (v[q] / norm);
        sq += y * y;
        __half h0 = __float2half_rn(y);
        float  r  = y - __half2float(h0);
        __half h1 = __float2half_rn(r);
        d0[lane + 32 * q] = h0;
        d1[lane + 32 * q] = h1;
    }
#pragma unroll
    for (int o = 16; o; o >>= 1) sq += __shfl_xor_sync(0xFFFFFFFFu, sq, o);
    if (lane == 0) {
        (which ? g_sq2 : g_sq1)[token] = sq;
        (which ? g_key2 : g_key1)[token] = ~0ULL;
    }
}

// -------- mma.sync fp16x2-split GEMM (3 products) + fused argmin ------------
// UNCHANGED mainloop (at the mma.sync dispatch roofline, 95% efficient).
__global__ void __launch_bounds__(256)
mma_argmin_kernel(const int* __restrict__ mask1, const int* __restrict__ mask2) {
    extern __shared__ char smem[];
    int bt = blockIdx.z, it = blockIdx.y, jt = blockIdx.x;
    int tid = threadIdx.x, wid = tid >> 5, lane = tid & 31;
    int warp_m = wid >> 2, warp_n = wid & 3;

    uint32_t sbase = smem_u32(smem);
    unsigned long long* s_row = (unsigned long long*)(smem + EPI_OFF);
    unsigned long long* s_col = (unsigned long long*)(smem + EPI_OFF + 1024);
    if (tid < 128) { s_row[tid] = ~0ULL; s_col[tid] = ~0ULL; }

    size_t offA = ((size_t)bt * HW + it * 128) * CDIM;
    size_t offB = ((size_t)bt * HW + jt * 128) * CDIM;
    const __half* srcs[4] = { g_h0a + offA, g_h1a + offA, g_h0b + offB, g_h1b + offB };

    int ft = tid >> 6, fs0 = tid & 63;
    const __half* fsrc = srcs[ft];
    uint32_t fdst0 = sbase + ft * TILE_HB;

    float acc[4][4][4];
#pragma unroll
    for (int mf = 0; mf < 4; mf++)
#pragma unroll
        for (int nf = 0; nf < 4; nf++)
#pragma unroll
            for (int v = 0; v < 4; v++) acc[mf][nf][v] = 0.f;

#pragma unroll
    for (int r = 0; r < 8; r++) {
        int s = fs0 + r * 64, row = s >> 2, seg = s & 3;
        cp_async16(fdst0 + row * 80 + seg * 16, fsrc + (size_t)row * CDIM + seg * 8);
    }
    asm volatile("cp.async.commit_group;" ::: "memory");
    asm volatile("cp.async.wait_group 0;" ::: "memory");
    __syncthreads();

    int lrow = lane & 15, lsel = (lane >> 4) << 3;
    int kswap = warp_m;

    for (int c = 0; c < NCHUNK; c++) {
        uint32_t buf = (uint32_t)(c & 1) * BUF_B;
        if (c < NCHUNK - 1) {
            uint32_t nbuf = (uint32_t)((c + 1) & 1) * BUF_B;
            int k0g = (c + 1) * KC;
#pragma unroll
            for (int r = 0; r < 8; r++) {
                int s = fs0 + r * 64, row = s >> 2, seg = s & 3;
                cp_async16(fdst0 + nbuf + row * 80 + seg * 16,
                           fsrc + (size_t)row * CDIM + k0g + seg * 8);
            }
            asm volatile("cp.async.commit_group;" ::: "memory");
        }
        uint32_t k0 = (uint32_t)(lsel + (kswap ? 16 : 0)) * 2;
        uint32_t k1 = (uint32_t)(lsel + (kswap ? 0 : 16)) * 2;
        uint32_t aRow = (uint32_t)(warp_m * 64 + lrow) * 80;
        uint32_t bRow = (uint32_t)(warp_n * 32 + lrow) * 80;
        uint32_t a0Base = sbase + buf + aRow;
        uint32_t a1Base = sbase + buf + TILE_HB + aRow;
        uint32_t b0Base = sbase + buf + 2 * TILE_HB + bRow;
        uint32_t b1Base = sbase + buf + 3 * TILE_HB + bRow;

        uint32_t A0[4][4], A1[4][4], B0[2][4], B1[2][4];
#pragma unroll
        for (int mf = 0; mf < 4; mf++) ldsm4(A0[mf], a0Base + k0 + (uint32_t)(mf * 16) * 80);
#pragma unroll
        for (int ng = 0; ng < 2; ng++) ldsm4(B0[ng], b0Base + k0 + (uint32_t)(ng * 16) * 80);

#pragma unroll
        for (int ng = 0; ng < 2; ng++) ldsm4(B1[ng], b1Base + k0 + (uint32_t)(ng * 16) * 80);
#pragma unroll
        for (int mf = 0; mf < 4; mf++)
#pragma unroll
            for (int nf = 0; nf < 4; nf++)
                mma16816(acc[mf][nf], A0[mf], B0[nf >> 1][nf & 1], B0[nf >> 1][(nf & 1) + 2]);

#pragma unroll
        for (int mf = 0; mf < 4; mf++) ldsm4(A1[mf], a1Base + k0 + (uint32_t)(mf * 16) * 80);
#pragma unroll
        for (int mf = 0; mf < 4; mf++)
#pragma unroll
            for (int nf = 0; nf < 4; nf++)
                mma16816(acc[mf][nf], A0[mf], B1[nf >> 1][nf & 1], B1[nf >> 1][(nf & 1) + 2]);

#pragma unroll
        for (int mf = 0; mf < 4; mf++) ldsm4(A0[mf], a0Base + k1 + (uint32_t)(mf * 16) * 80);
#pragma unroll
        for (int ng = 0; ng < 2; ng++) ldsm4(B1[ng], b0Base + k1 + (uint32_t)(ng * 16) * 80);
#pragma unroll
        for (int mf = 0; mf < 4; mf++)
#pragma unroll
            for (int nf = 0; nf < 4; nf++)
                mma16816(acc[mf][nf], A1[mf], B0[nf >> 1][nf & 1], B0[nf >> 1][(nf & 1) + 2]);

#pragma unroll
        for (int ng = 0; ng < 2; ng++) ldsm4(B0[ng], b1Base + k1 + (uint32_t)(ng * 16) * 80);
#pragma unroll
        for (int mf = 0; mf < 4; mf++)
#pragma unroll
            for (int nf = 0; nf < 4; nf++)
                mma16816(acc[mf][nf], A0[mf], B1[nf >> 1][nf & 1], B1[nf >> 1][(nf & 1) + 2]);

#pragma unroll
        for (int mf = 0; mf < 4; mf++) ldsm4(A1[mf], a1Base + k1 + (uint32_t)(mf * 16) * 80);
#pragma unroll
        for (int mf = 0; mf < 4; mf++)
#pragma unroll
            for (int nf = 0; nf < 4; nf++)
                mma16816(acc[mf][nf], A0[mf], B0[nf >> 1][nf & 1], B0[nf >> 1][(nf & 1) + 2]);

#pragma unroll
        for (int mf = 0; mf < 4; mf++)
#pragma unroll
            for (int nf = 0; nf < 4; nf++)
                mma16816(acc[mf][nf], A1[mf], B1[nf >> 1][nf & 1], B1[nf >> 1][(nf & 1) + 2]);

        asm volatile("cp.async.wait_group 0;" ::: "memory");
        __syncthreads();
    }

    // ---- epilogue ----
    int   m1v[8], m2v[8];
    float sq1v[8], sq2v[8];
#pragma unroll
    for (int mf = 0; mf < 4; mf++)
#pragma unroll
        for (int h = 0; h < 2; h++) {
            int rl = warp_m * 64 + mf * 16 + (lane >> 2) + 8 * h;
            m1v[mf * 2 + h]  = mask1[bt * HW + it * 128 + rl];
            sq1v[mf * 2 + h] = g_sq1[bt * HW + it * 128 + rl];
        }
#pragma unroll
    for (int nf = 0; nf < 4; nf++)
#pragma unroll
        for (int h = 0; h < 2; h++) {
            int cl = warp_n * 32 + nf * 8 + (lane & 3) * 2 + h;
            m2v[nf * 2 + h]  = mask2[bt * HW + jt * 128 + cl];
            sq2v[nf * 2 + h] = g_sq2[bt * HW + jt * 128 + cl];
        }

    unsigned long long rowbest[8], colbest[8];
#pragma unroll
    for (int q = 0; q < 8; q++) { rowbest[q] = ~0ULL; colbest[q] = ~0ULL; }

#pragma unroll
    for (int mf = 0; mf < 4; mf++)
#pragma unroll
        for (int nf = 0; nf < 4; nf++)
#pragma unroll
            for (int v = 0; v < 4; v++) {
                int ri = mf * 2 + (v >> 1);
                int ci = nf * 2 + (v & 1);
                int rl = warp_m * 64 + mf * 16 + (lane >> 2) + 8 * (v >> 1);
                int cl = warp_n * 32 + nf * 8 + (lane & 3) * 2 + (v & 1);
                float dot = acc[mf][nf][v];
                bool ok = (m1v[ri] > 0) && (m2v[ci] > 0);
                float d = ok ? sqrtf(fmaxf(sq1v[ri] + sq2v[ci] - 2.f * dot, 0.f)) : 1.0e7f;
                unsigned long long hb = ((unsigned long long)__float_as_uint(d) << 32);
                unsigned long long kr = hb | (unsigned)(jt * 128 + cl);
                unsigned long long kc = hb | (unsigned)(it * 128 + rl);
                rowbest[ri] = kr < rowbest[ri] ? kr : rowbest[ri];
                colbest[ci] = kc < colbest[ci] ? kc : colbest[ci];
            }

#pragma unroll
    for (int q = 0; q < 8; q++) {
#pragma unroll
        for (int o = 1; o < 4; o <<= 1) {
            unsigned long long t = __shfl_xor_sync(0xFFFFFFFFu, rowbest[q], o);
            rowbest[q] = t < rowbest[q] ? t : rowbest[q];
        }
        if ((lane & 3) == 0) {
            int rl = warp_m * 64 + (q >> 1) * 16 + (lane >> 2) + 8 * (q & 1);
            atomicMin(&s_row[rl], rowbest[q]);
        }
    }
#pragma unroll
    for (int q = 0; q < 8; q++) {
#pragma unroll
        for (int o = 4; o < 32; o <<= 1) {
            unsigned long long t = __shfl_xor_sync(0xFFFFFFFFu, colbest[q], o);
            colbest[q] = t < colbest[q] ? t : colbest[q];
        }
        if ((lane >> 2) == 0) {
            int cl = warp_n * 32 + (q >> 1) * 8 + (lane & 3) * 2 + (q & 1);
            atomicMin(&s_col[cl], colbest[q]);
        }
    }
    __syncthreads();
    if (tid < 128) {
        atomicMin(&g_key1[bt * HW + it * 128 + tid], s_row[tid]);
        atomicMin(&g_key2[bt * HW + jt * 128 + tid], s_col[tid]);
    }
}

// ------- cyclic diff + stable top-128 via counting selection ----------------
// d2 is an integer <= 7938; sentinel bucket 8191 for invalid (BIG_DIFF).
// Ordering == jax top_k: (d2 asc, index asc).
#define NBUCK 8192
__global__ void __launch_bounds__(512)
topk_kernel(const int* __restrict__ mask1, const int* __restrict__ mask2,
            const int* __restrict__ backup1, const int* __restrict__ backup2,
            float* __restrict__ out) {
    int b   = blockIdx.x >> 1;
    int dir = blockIdx.x & 1;
    const unsigned long long* keyF  = dir ? g_key2 : g_key1;
    const unsigned long long* keyBk = dir ? g_key1 : g_key2;
    const int* mSrc   = dir ? mask2   : mask1;
    const int* mDst   = dir ? mask1   : mask2;
    const int* backup = dir ? backup2 : backup1;

    __shared__ unsigned short s_d2[HW];            // 8 KB
    __shared__ int s_hist[NBUCK];                  // 32 KB
    __shared__ int s_part[512];                    // 2 KB
    __shared__ unsigned long long s_list[KSEL];    // 1 KB
    __shared__ int s_misc[4];                      // cnt, T, n1, nlist

    int tid = threadIdx.x;
    if (tid < 4) s_misc[tid] = 0;
#pragma unroll
    for (int q = 0; q < NBUCK / 512; q++) s_hist[tid + q * 512] = 0;
    __syncthreads();

    int outBase = dir * (BATCH * KSEL * 2) + b * (KSEL * 2);

    // pass 1: d2 per element (blocked layout for stable scans) + histogram + cnt
    int cnt = 0;
#pragma unroll
    for (int q = 0; q < HW / 512; q++) {
        int i = tid * (HW / 512) + q;              // blocked: preserves index order
        int srcm = mSrc[b * HW + i];
        cnt += (srcm > 0);
        int mf = (int)(keyF[b * HW + i] & 0xFFFFFFFFull);
        unsigned d2;
        if (srcm > 0 && mDst[b * HW + mf] > 0) {
            int cyc = (int)(keyBk[b * HW + mf] & 0xFFFFFFFFull);
            int dx = (cyc >> 6) - (i >> 6);
            int dy = (cyc & 63) - (i & 63);
            d2 = (unsigned)(dx * dx + dy * dy);    // <= 7938
        } else {
            d2 = NBUCK - 1;                        // sentinel (BIG_DIFF)
        }
        s_d2[i] = (unsigned short)d2;
        atomicAdd(&s_hist[d2], 1);
    }
#pragma unroll
    for (int o = 16; o; o >>= 1) cnt += __shfl_xor_sync(0xFFFFFFFFu, cnt, o);
    if ((tid & 31) == 0) atomicAdd(&s_misc[0], cnt);
    __syncthreads();

    // scan histogram (16 buckets/thread) to locate threshold bucket T
    int hsum = 0;
#pragma unroll
    for (int q = 0; q < 16; q++) hsum += s_hist[tid * 16 + q];
    s_part[tid] = hsum;
    __syncthreads();
    for (int off = 1; off < 512; off <<= 1) {
        int v = (tid >= off) ? s_part[tid - off] : 0;
        __syncthreads();
        s_part[tid] += v;
        __syncthreads();
    }
    int hbase = s_part[tid] - hsum;                // exclusive prefix for this thread's range
    if (hbase < KSEL && hbase + hsum >= KSEL) {    // exactly one thread
        int c = hbase;
#pragma unroll
        for (int q = 0; q < 16; q++) {
            int h = s_hist[tid * 16 + q];
            if (c + h >= KSEL) { s_misc[1] = tid * 16 + q; s_misc[2] = c; break; }
            c += h;
        }
    }
    __syncthreads();

    bool useTop = (s_misc[0] >= KSEL);
    if (useTop) {
        int T = s_misc[1], n1 = s_misc[2];         // n1 = #elements with d2 < T  (< 128)
        // collect strict-below elements, sort (d2, idx) with 128-wide bitonic
        for (int q = 0; q < HW / 512; q++) {
            int i = tid * (HW / 512) + q;
            if (s_d2[i] < T) {
                int p = atomicAdd(&s_misc[3], 1);
                s_list[p] = ((unsigned long long)s_d2[i] << 32) | (unsigned)i;
            }
        }
        __syncthreads();
        if (tid >= n1 && tid < KSEL) s_list[tid] = ~0ULL;
        __syncthreads();
        for (int k = 2; k <= KSEL; k <<= 1)
            for (int j = k >> 1; j > 0; j >>= 1) {
                if (tid < KSEL) {
                    int ixj = tid ^ j;
                    if (ixj > tid) {
                        unsigned long long a = s_list[tid], c2 = s_list[ixj];
                        bool up = ((tid & k) == 0);
                        if ((a > c2) == up) { s_list[tid] = c2; s_list[ixj] = a; }
                    }
                }
                __syncthreads();
            }
        if (tid < n1) {
            int idx = (int)(s_list[tid] & 0xFFFFFFFFull);
            int match = (int)(keyF[b * HW + idx] & 0xFFFFFFFFull);
            out[outBase + tid * 2]     = (float)idx;
            out[outBase + tid * 2 + 1] = (float)match;
        }
        // stable compaction of the threshold bucket (index-ascending)
        int myf[HW / 512], fsum = 0;
#pragma unroll
        for (int q = 0; q < HW / 512; q++) {
            int i = tid * (HW / 512) + q;
            myf[q] = (s_d2[i] == T);
            fsum += myf[q];
        }
        __syncthreads();
        s_part[tid] = fsum;
        __syncthreads();
        for (int off = 1; off < 512; off <<= 1) {
            int v = (tid >= off) ? s_part[tid - off] : 0;
            __syncthreads();
            s_part[tid] += v;
            __syncthreads();
        }
        int p = s_part[tid] - fsum;
        int need = KSEL - n1;
#pragma unroll
        for (int q = 0; q < HW / 512; q++) {
            if (myf[q]) {
                if (p < need) {
                    int i = tid * (HW / 512) + q;
                    int match = (int)(keyF[b * HW + i] & 0xFFFFFFFFull);
                    out[outBase + (n1 + p) * 2]     = (float)i;
                    out[outBase + (n1 + p) * 2 + 1] = (float)match;
                }
                p++;
            }
        }
    } else {
        if (tid < KSEL) {
            int idx = backup[b * KSEL + tid];
            int match = (int)(keyF[b * HW + idx] & 0xFFFFFFFFull);
            out[outBase + tid * 2]     = (float)idx;
            out[outBase + tid * 2 + 1] = (float)match;
        }
    }
}

// ---------------- launch ----------------------------------------------------
extern "C" void kernel_launch(void* const* d_in, const int* in_sizes, int n_in,
                              void* d_out, int out_size) {
    const float* f1 = nullptr; const float* f2 = nullptr;
    const int* mask1 = nullptr; const int* mask2 = nullptr;
    const int* bk1 = nullptr; const int* bk2 = nullptr;
    for (int i = 0; i < n_in; i++) {
        long long sz = in_sizes[i];
        if (sz == FEAT_N || sz == (long long)FEAT_N * 4) {
            if (!f1) f1 = (const float*)d_in[i]; else f2 = (const float*)d_in[i];
        } else if (sz == MASK_N || sz == (long long)MASK_N * 4) {
            if (!mask1) mask1 = (const int*)d_in[i]; else mask2 = (const int*)d_in[i];
        } else if (sz == BK_N || sz == (long long)BK_N * 4) {
            if (!bk1) bk1 = (const int*)d_in[i]; else bk2 = (const int*)d_in[i];
        }
    }
    if (!f1 || !f2 || !mask1 || !mask2 || !bk1 || !bk2) {
        f1    = (const float*)d_in[0];
        f2    = (const float*)d_in[1];
        mask1 = (const int*)d_in[2];
        mask2 = (const int*)d_in[3];
        bk1   = (const int*)d_in[4];
        bk2   = (const int*)d_in[5];
    }
    float* out = (float*)d_out;

    cudaFuncSetAttribute(mma_argmin_kernel,
                         cudaFuncAttributeMaxDynamicSharedMemorySize, SMEM_DYN);

    normalize_kernel<<<2 * (MASK_N / 8), 256>>>(f1, f2, mask1, mask2);
    dim3 grid(HW / 128, HW / 128, BATCH);
    mma_argmin_kernel<<<grid, 256, SMEM_DYN>>>(mask1, mask2);
    topk_kernel<<<BATCH * 2, 512>>>(mask1, mask2, bk1, bk2, out);
}

// round 14
// speedup vs baseline: 4.7044x; 1.8983x over previous
#include <cuda_runtime.h>
#include <cuda_fp16.h>
#include <stdint.h>

#define BATCH 8
#define HW    4096
#define CDIM  384
#define KSEL  128

#define FEAT_N (BATCH * HW * CDIM)   // 12582912
#define MASK_N (BATCH * HW)          // 32768
#define BK_N   (BATCH * KSEL)        // 1024

#define KC       32
#define NCHUNK   (CDIM / KC)         // 12
#define TILE_HB  (128 * 40 * 2)      // 10240 B per 128x32 half tile (80B rows)
#define BUF_B    (2 * TILE_HB)       // a0,b0 per stage = 20480
#define SD2_STRH 136                 // smem d2 row stride (halfs): 68 words, 68%32=4 -> conflict-free
#define SD2_B    (128 * SD2_STRH * 2)  // 34816
#define SROWCOL  40960               // s_row/s_col offset (after mma bufs; s_d2 overlays bufs)
#define SMEM_P1  (SROWCOL + 1024)

#define EPS      0.015f
#define SENT     30000.0f
#define CAND_CAP (1 << 22)

// ---------------- scratch ----------------------------------------------------
__device__ __half g_h0a[FEAT_N], g_h0b[FEAT_N];    // fp16 leading parts
__device__ float  g_f1[FEAT_N],  g_f2[FEAT_N];     // fp32 normalized (refine)
__device__ float  g_sq1[MASK_N], g_sq2[MASK_N];
__device__ unsigned g_rowmin[MASK_N], g_colmin[MASK_N];   // fp32 bits (>=0)
__device__ unsigned long long g_key1[MASK_N], g_key2[MASK_N];
__device__ __half g_d2[(size_t)BATCH * HW * HW];   // 256 MB approx d2
__device__ unsigned g_cand[CAND_CAP];
__device__ int g_ncand;

// ---------------- helpers ----------------------------------------------------
__device__ __forceinline__ uint32_t smem_u32(const void* p) {
    uint32_t a;
    asm("{ .reg .u64 t; cvta.to.shared.u64 t, %1; cvt.u32.u64 %0, t; }" : "=r"(a) : "l"(p));
    return a;
}
__device__ __forceinline__ void cp_async16(uint32_t dst, const void* src) {
    asm volatile("cp.async.cg.shared.global [%0], [%1], 16;" :: "r"(dst), "l"(src) : "memory");
}
__device__ __forceinline__ void ldsm4(uint32_t* r, uint32_t a) {
    asm volatile("ldmatrix.sync.aligned.m8n8.x4.shared.b16 {%0,%1,%2,%3}, [%4];"
                 : "=r"(r[0]), "=r"(r[1]), "=r"(r[2]), "=r"(r[3]) : "r"(a));
}
__device__ __forceinline__ void mma16816(float* c, const uint32_t* a, uint32_t b0, uint32_t b1) {
    asm volatile(
        "mma.sync.aligned.m16n8k16.row.col.f32.f16.f16.f32 "
        "{%0,%1,%2,%3}, {%4,%5,%6,%7}, {%8,%9}, {%0,%1,%2,%3};"
        : "+f"(c[0]), "+f"(c[1]), "+f"(c[2]), "+f"(c[3])
        : "r"(a[0]), "r"(a[1]), "r"(a[2]), "r"(a[3]), "r"(b0), "r"(b1));
}

// ------ normalize: fp16 h0 + fp32 y + sq + init mins/keys/counter -----------
__global__ void normalize_kernel(const float* __restrict__ fa, const float* __restrict__ fb,
                                 const int* __restrict__ ma, const int* __restrict__ mb) {
    if (blockIdx.x == 0 && threadIdx.x == 0) g_ncand = 0;
    int half = gridDim.x >> 1;
    int which = blockIdx.x >= half;
    int blk   = which ? blockIdx.x - half : blockIdx.x;
    const float* f    = which ? fb : fa;
    const int*   mask = which ? mb : ma;

    int token = blk * 8 + (threadIdx.x >> 5);
    int lane  = threadIdx.x & 31;
    if (token >= MASK_N) return;
    const float* src = f + (size_t)token * CDIM;
    float v[12];
    float s = 0.f;
#pragma unroll
    for (int q = 0; q < 12; q++) { v[q] = src[lane + 32 * q]; s += v[q] * v[q]; }
#pragma unroll
    for (int o = 16; o; o >>= 1) s += __shfl_xor_sync(0xFFFFFFFFu, s, o);
    float norm = sqrtf(s);
    float m = (mask[token] > 0) ? 1.f : 0.f;
    __half* d0 = (which ? g_h0b : g_h0a) + (size_t)token * CDIM;
    float*  df = (which ? g_f2  : g_f1)  + (size_t)token * CDIM;
    float sq = 0.f;
#pragma unroll
    for (int q = 0; q < 12; q++) {
        float y = m * (v[q] / norm);
        sq += y * y;
        d0[lane + 32 * q] = __float2half_rn(y);
        df[lane + 32 * q] = y;
    }
#pragma unroll
    for (int o = 16; o; o >>= 1) sq += __shfl_xor_sync(0xFFFFFFFFu, sq, o);
    if (lane == 0) {
        (which ? g_sq2 : g_sq1)[token] = sq;
        (which ? g_key2 : g_key1)[token] = ~0ULL;
        (which ? g_colmin : g_rowmin)[token] = 0x7F7FFFFFu;   // +FLT_MAX bits
        (which ? g_rowmin : g_colmin)[token] = 0x7F7FFFFFu;   // init both (idempotent)
    }
}

// ------------- pass 1: single-product GEMM + d2 store + row/col mins --------
__global__ void __launch_bounds__(256)
mma_d2_kernel(const int* __restrict__ mask1, const int* __restrict__ mask2) {
    extern __shared__ char smem[];
    int bt = blockIdx.z, it = blockIdx.y, jt = blockIdx.x;
    int tid = threadIdx.x, wid = tid >> 5, lane = tid & 31;
    int warp_m = wid >> 2, warp_n = wid & 3;

    uint32_t sbase = smem_u32(smem);
    unsigned* s_rmin = (unsigned*)(smem + SROWCOL);
    unsigned* s_cmin = (unsigned*)(smem + SROWCOL + 512);
    __half* s_d2 = (__half*)smem;                         // overlays mma bufs (used post-loop)
    if (tid < 128) { s_rmin[tid] = 0x7F7FFFFFu; s_cmin[tid] = 0x7F7FFFFFu; }

    size_t offA = ((size_t)bt * HW + it * 128) * CDIM;
    size_t offB = ((size_t)bt * HW + jt * 128) * CDIM;
    const __half* srcs[2] = { g_h0a + offA, g_h0b + offB };

    int ft = tid >> 7, fs0 = tid & 127;
    const __half* fsrc = srcs[ft];
    uint32_t fdst0 = sbase + ft * TILE_HB;

    float acc[4][4][4];
#pragma unroll
    for (int mf = 0; mf < 4; mf++)
#pragma unroll
        for (int nf = 0; nf < 4; nf++)
#pragma unroll
            for (int v = 0; v < 4; v++) acc[mf][nf][v] = 0.f;

#pragma unroll
    for (int r = 0; r < 4; r++) {
        int s = fs0 + r * 128, row = s >> 2, seg = s & 3;
        cp_async16(fdst0 + row * 80 + seg * 16, fsrc + (size_t)row * CDIM + seg * 8);
    }
    asm volatile("cp.async.commit_group;" ::: "memory");
    asm volatile("cp.async.wait_group 0;" ::: "memory");
    __syncthreads();

    int lrow = lane & 15, lsel = (lane >> 4) << 3;
    int kswap = warp_m;

    for (int c = 0; c < NCHUNK; c++) {
        uint32_t buf = (uint32_t)(c & 1) * BUF_B;
        if (c < NCHUNK - 1) {
            uint32_t nbuf = (uint32_t)((c + 1) & 1) * BUF_B;
            int k0g = (c + 1) * KC;
#pragma unroll
            for (int r = 0; r < 4; r++) {
                int s = fs0 + r * 128, row = s >> 2, seg = s & 3;
                cp_async16(fdst0 + nbuf + row * 80 + seg * 16,
                           fsrc + (size_t)row * CDIM + k0g + seg * 8);
            }
            asm volatile("cp.async.commit_group;" ::: "memory");
        }
        uint32_t aBase = sbase + buf + (uint32_t)(warp_m * 64 + lrow) * 80;
        uint32_t bBase = sbase + buf + TILE_HB + (uint32_t)(warp_n * 32 + lrow) * 80;
#pragma unroll
        for (int kk = 0; kk < 2; kk++) {
            uint32_t kb = (uint32_t)(((kk ^ kswap) ? 16 : 0) + lsel) * 2;
            uint32_t A0[4][4], B0[2][4];
#pragma unroll
            for (int mf = 0; mf < 4; mf++) ldsm4(A0[mf], aBase + kb + (uint32_t)(mf * 16) * 80);
#pragma unroll
            for (int ng = 0; ng < 2; ng++) ldsm4(B0[ng], bBase + kb + (uint32_t)(ng * 16) * 80);
#pragma unroll
            for (int mf = 0; mf < 4; mf++)
#pragma unroll
                for (int nf = 0; nf < 4; nf++)
                    mma16816(acc[mf][nf], A0[mf], B0[nf >> 1][nf & 1], B0[nf >> 1][(nf & 1) + 2]);
        }
        asm volatile("cp.async.wait_group 0;" ::: "memory");
        __syncthreads();
    }

    // ---- epilogue: d2 = clamp(sq1+sq2-2dot, 0) or SENT; store + mins ----
    int   m1v[8], m2v[8];
    float sq1v[8], sq2v[8];
#pragma unroll
    for (int mf = 0; mf < 4; mf++)
#pragma unroll
        for (int h = 0; h < 2; h++) {
            int rl = warp_m * 64 + mf * 16 + (lane >> 2) + 8 * h;
            m1v[mf * 2 + h]  = mask1[bt * HW + it * 128 + rl];
            sq1v[mf * 2 + h] = g_sq1[bt * HW + it * 128 + rl];
        }
#pragma unroll
    for (int nf = 0; nf < 4; nf++)
#pragma unroll
        for (int h = 0; h < 2; h++) {
            int cl = warp_n * 32 + nf * 8 + (lane & 3) * 2 + h;
            m2v[nf * 2 + h]  = mask2[bt * HW + jt * 128 + cl];
            sq2v[nf * 2 + h] = g_sq2[bt * HW + jt * 128 + cl];
        }

    float rowbest[8], colbest[8];
#pragma unroll
    for (int q = 0; q < 8; q++) { rowbest[q] = 3.4e38f; colbest[q] = 3.4e38f; }

    float d2s[4][4][4];
#pragma unroll
    for (int mf = 0; mf < 4; mf++)
#pragma unroll
        for (int nf = 0; nf < 4; nf++)
#pragma unroll
            for (int v = 0; v < 4; v++) {
                int ri = mf * 2 + (v >> 1);
                int ci = nf * 2 + (v & 1);
                bool ok = (m1v[ri] > 0) && (m2v[ci] > 0);
                float d2 = ok ? fmaxf(sq1v[ri] + sq2v[ci] - 2.f * acc[mf][nf][v], 0.f) : SENT;
                d2s[mf][nf][v] = d2;
                rowbest[ri] = fminf(rowbest[ri], d2);
                colbest[ci] = fminf(colbest[ci], d2);
            }

    // write d2 to smem (conflict-free stride), then coalesced STG
#pragma unroll
    for (int mf = 0; mf < 4; mf++)
#pragma unroll
        for (int nf = 0; nf < 4; nf++)
#pragma unroll
            for (int h = 0; h < 2; h++) {
                int rl = warp_m * 64 + mf * 16 + (lane >> 2) + 8 * h;
                int cl0 = warp_n * 32 + nf * 8 + (lane & 3) * 2;
                __half2 pk = __floats2half2_rn(d2s[mf][nf][2 * h], d2s[mf][nf][2 * h + 1]);
                *(__half2*)(s_d2 + rl * SD2_STRH + cl0) = pk;
            }

    // row/col reductions -> smem atomics
#pragma unroll
    for (int q = 0; q < 8; q++) {
#pragma unroll
        for (int o = 1; o < 4; o <<= 1)
            rowbest[q] = fminf(rowbest[q], __shfl_xor_sync(0xFFFFFFFFu, rowbest[q], o));
        if ((lane & 3) == 0) {
            int rl = warp_m * 64 + (q >> 1) * 16 + (lane >> 2) + 8 * (q & 1);
            atomicMin(&s_rmin[rl], __float_as_uint(rowbest[q]));
        }
#pragma unroll
        for (int o = 4; o < 32; o <<= 1)
            colbest[q] = fminf(colbest[q], __shfl_xor_sync(0xFFFFFFFFu, colbest[q], o));
        if ((lane >> 2) == 0) {
            int cl = warp_n * 32 + (q >> 1) * 8 + (lane & 3) * 2 + (q & 1);
            atomicMin(&s_cmin[cl], __float_as_uint(colbest[q]));
        }
    }
    __syncthreads();

    // coalesced d2 store: 2048 float4, 8 per thread
    __half* gout = g_d2 + (size_t)bt * HW * HW + (size_t)(it * 128) * HW + jt * 128;
#pragma unroll
    for (int q = 0; q < 8; q++) {
        int f = tid + q * 256;
        int r = f >> 4, c16 = f & 15;
        float4 val = *(const float4*)(s_d2 + r * SD2_STRH + c16 * 8);
        *(float4*)(gout + (size_t)r * HW + c16 * 8) = val;
    }
    if (tid < 128) {
        atomicMin(&g_rowmin[bt * HW + it * 128 + tid], s_rmin[tid]);
        atomicMin(&g_colmin[bt * HW + jt * 128 + tid], s_cmin[tid]);
    }
}

// ------------- pass 2: scan d2, emit candidates -----------------------------
__global__ void __launch_bounds__(128)
scan_kernel() {
    int bi = blockIdx.x;                 // bt*HW + i
    int bt = bi >> 12, i = bi & 4095;
    int tid = threadIdx.x;
    float rm = __uint_as_float(g_rowmin[bi]) + EPS;
    const __half* row = g_d2 + (size_t)bt * HW * HW + (size_t)i * HW;
    const unsigned* cmin = g_colmin + bt * HW;
#pragma unroll
    for (int q = 0; q < 4; q++) {
        int f = tid + q * 128;           // float4 index; j0 = f*8
        float4 raw = *(const float4*)(row + f * 8);
        const __half2* h2 = (const __half2*)&raw;
#pragma unroll
        for (int p = 0; p < 4; p++) {
            float2 d = __half22float2(h2[p]);
#pragma unroll
            for (int e = 0; e < 2; e++) {
                float d2v = e ? d.y : d.x;
                if (d2v < 20000.f) {
                    int j = f * 8 + p * 2 + e;
                    bool fr = d2v <= rm;
                    bool fc = d2v <= __uint_as_float(cmin[j]) + EPS;
                    if (fr || fc) {
                        unsigned w = (fr ? (1u << 27) : 0) | (fc ? (1u << 28) : 0) |
                                     ((unsigned)bt << 24) | ((unsigned)i << 12) | (unsigned)j;
                        int p0 = atomicAdd(&g_ncand, 1);
                        if (p0 < CAND_CAP) g_cand[p0] = w;
                    }
                }
            }
        }
    }
}

// ------------- pass 3: sentinel fixup + exact refine ------------------------
__global__ void __launch_bounds__(256)
refine_kernel() {
    int tid = threadIdx.x, lane = tid & 31;
    int gw = blockIdx.x * 8 + (tid >> 5);         // global warp id (2048*8 = 16384)
    int gt = blockIdx.x * 256 + tid;
    if (gt < MASK_N) {
        unsigned long long sk = ((unsigned long long)__float_as_uint(1.0e7f) << 32);
        if (__uint_as_float(g_rowmin[gt]) >= 20000.f) g_key1[gt] = sk;   // argmin -> index 0
        if (__uint_as_float(g_colmin[gt]) >= 20000.f) g_key2[gt] = sk;
    }
    int n = g_ncand; if (n > CAND_CAP) n = CAND_CAP;
    for (int c = gw; c < n; c += 16384) {
        unsigned w = g_cand[c];
        int j = w & 4095, i = (w >> 12) & 4095, bt = (w >> 24) & 7;
        const float* y1 = g_f1 + ((size_t)bt * HW + i) * CDIM;
        const float* y2 = g_f2 + ((size_t)bt * HW + j) * CDIM;
        float dot = 0.f;
#pragma unroll
        for (int q = 0; q < 3; q++) {
            int f = lane + 32 * q;
            float4 a = *(const float4*)(y1 + f * 4);
            float4 b = *(const float4*)(y2 + f * 4);
            dot += a.x * b.x + a.y * b.y + a.z * b.z + a.w * b.w;
        }
#pragma unroll
        for (int o = 16; o; o >>= 1) dot += __shfl_xor_sync(0xFFFFFFFFu, dot, o);
        if (lane == 0) {
            float d = sqrtf(fmaxf(g_sq1[bt * HW + i] + g_sq2[bt * HW + j] - 2.f * dot, 0.f));
            unsigned long long hb = ((unsigned long long)__float_as_uint(d) << 32);
            if (w & (1u << 27)) atomicMin(&g_key1[bt * HW + i], hb | (unsigned)j);
            if (w & (1u << 28)) atomicMin(&g_key2[bt * HW + j], hb | (unsigned)i);
        }
    }
}

// ------- cyclic diff + stable top-128 via counting selection ----------------
#define NBUCK 8192
__global__ void __launch_bounds__(512)
topk_kernel(const int* __restrict__ mask1, const int* __restrict__ mask2,
            const int* __restrict__ backup1, const int* __restrict__ backup2,
            float* __restrict__ out) {
    int b   = blockIdx.x >> 1;
    int dir = blockIdx.x & 1;
    const unsigned long long* keyF  = dir ? g_key2 : g_key1;
    const unsigned long long* keyBk = dir ? g_key1 : g_key2;
    const int* mSrc   = dir ? mask2   : mask1;
    const int* mDst   = dir ? mask1   : mask2;
    const int* backup = dir ? backup2 : backup1;

    __shared__ unsigned short s_d2[HW];
    __shared__ int s_hist[NBUCK];
    __shared__ int s_part[512];
    __shared__ unsigned long long s_list[KSEL];
    __shared__ int s_misc[4];

    int tid = threadIdx.x;
    if (tid < 4) s_misc[tid] = 0;
#pragma unroll
    for (int q = 0; q < NBUCK / 512; q++) s_hist[tid + q * 512] = 0;
    __syncthreads();

    int outBase = dir * (BATCH * KSEL * 2) + b * (KSEL * 2);

    int cnt = 0;
#pragma unroll
    for (int q = 0; q < HW / 512; q++) {
        int i = tid * (HW / 512) + q;
        int srcm = mSrc[b * HW + i];
        cnt += (srcm > 0);
        int mf = (int)(keyF[b * HW + i] & 0xFFFFFFFFull);
        unsigned d2;
        if (srcm > 0 && mDst[b * HW + mf] > 0) {
            int cyc = (int)(keyBk[b * HW + mf] & 0xFFFFFFFFull);
            int dx = (cyc >> 6) - (i >> 6);
            int dy = (cyc & 63) - (i & 63);
            d2 = (unsigned)(dx * dx + dy * dy);
        } else {
            d2 = NBUCK - 1;
        }
        s_d2[i] = (unsigned short)d2;
        atomicAdd(&s_hist[d2], 1);
    }
#pragma unroll
    for (int o = 16; o; o >>= 1) cnt += __shfl_xor_sync(0xFFFFFFFFu, cnt, o);
    if ((tid & 31) == 0) atomicAdd(&s_misc[0], cnt);
    __syncthreads();

    int hsum = 0;
#pragma unroll
    for (int q = 0; q < 16; q++) hsum += s_hist[tid * 16 + q];
    s_part[tid] = hsum;
    __syncthreads();
    for (int off = 1; off < 512; off <<= 1) {
        int v = (tid >= off) ? s_part[tid - off] : 0;
        __syncthreads();
        s_part[tid] += v;
        __syncthreads();
    }
    int hbase = s_part[tid] - hsum;
    if (hbase < KSEL && hbase + hsum >= KSEL) {
        int c = hbase;
#pragma unroll
        for (int q = 0; q < 16; q++) {
            int h = s_hist[tid * 16 + q];
            if (c + h >= KSEL) { s_misc[1] = tid * 16 + q; s_misc[2] = c; break; }
            c += h;
        }
    }
    __syncthreads();

    bool useTop = (s_misc[0] >= KSEL);
    if (useTop) {
        int T = s_misc[1], n1 = s_misc[2];
        for (int q = 0; q < HW / 512; q++) {
            int i = tid * (HW / 512) + q;
            if (s_d2[i] < T) {
                int p = atomicAdd(&s_misc[3], 1);
                s_list[p] = ((unsigned long long)s_d2[i] << 32) | (unsigned)i;
            }
        }
        __syncthreads();
        if (tid >= n1 && tid < KSEL) s_list[tid] = ~0ULL;
        __syncthreads();
        for (int k = 2; k <= KSEL; k <<= 1)
            for (int j = k >> 1; j > 0; j >>= 1) {
                if (tid < KSEL) {
                    int ixj = tid ^ j;
                    if (ixj > tid) {
                        unsigned long long a = s_list[tid], c2 = s_list[ixj];
                        bool up = ((tid & k) == 0);
                        if ((a > c2) == up) { s_list[tid] = c2; s_list[ixj] = a; }
                    }
                }
                __syncthreads();
            }
        if (tid < n1) {
            int idx = (int)(s_list[tid] & 0xFFFFFFFFull);
            int match = (int)(keyF[b * HW + idx] & 0xFFFFFFFFull);
            out[outBase + tid * 2]     = (float)idx;
            out[outBase + tid * 2 + 1] = (float)match;
        }
        int myf[HW / 512], fsum = 0;
#pragma unroll
        for (int q = 0; q < HW / 512; q++) {
            int i = tid * (HW / 512) + q;
            myf[q] = (s_d2[i] == T);
            fsum += myf[q];
        }
        __syncthreads();
        s_part[tid] = fsum;
        __syncthreads();
        for (int off = 1; off < 512; off <<= 1) {
            int v = (tid >= off) ? s_part[tid - off] : 0;
            __syncthreads();
            s_part[tid] += v;
            __syncthreads();
        }
        int p = s_part[tid] - fsum;
        int need = KSEL - n1;
#pragma unroll
        for (int q = 0; q < HW / 512; q++) {
            if (myf[q]) {
                if (p < need) {
                    int i = tid * (HW / 512) + q;
                    int match = (int)(keyF[b * HW + i] & 0xFFFFFFFFull);
                    out[outBase + (n1 + p) * 2]     = (float)i;
                    out[outBase + (n1 + p) * 2 + 1] = (float)match;
                }
                p++;
            }
        }
    } else {
        if (tid < KSEL) {
            int idx = backup[b * KSEL + tid];
            int match = (int)(keyF[b * HW + idx] & 0xFFFFFFFFull);
            out[outBase + tid * 2]     = (float)idx;
            out[outBase + tid * 2 + 1] = (float)match;
        }
    }
}

// ---------------- launch ----------------------------------------------------
extern "C" void kernel_launch(void* const* d_in, const int* in_sizes, int n_in,
                              void* d_out, int out_size) {
    const float* f1 = nullptr; const float* f2 = nullptr;
    const int* mask1 = nullptr; const int* mask2 = nullptr;
    const int* bk1 = nullptr; const int* bk2 = nullptr;
    for (int i = 0; i < n_in; i++) {
        long long sz = in_sizes[i];
        if (sz == FEAT_N || sz == (long long)FEAT_N * 4) {
            if (!f1) f1 = (const float*)d_in[i]; else f2 = (const float*)d_in[i];
        } else if (sz == MASK_N || sz == (long long)MASK_N * 4) {
            if (!mask1) mask1 = (const int*)d_in[i]; else mask2 = (const int*)d_in[i];
        } else if (sz == BK_N || sz == (long long)BK_N * 4) {
            if (!bk1) bk1 = (const int*)d_in[i]; else bk2 = (const int*)d_in[i];
        }
    }
    if (!f1 || !f2 || !mask1 || !mask2 || !bk1 || !bk2) {
        f1    = (const float*)d_in[0];
        f2    = (const float*)d_in[1];
        mask1 = (const int*)d_in[2];
        mask2 = (const int*)d_in[3];
        bk1   = (const int*)d_in[4];
        bk2   = (const int*)d_in[5];
    }
    float* out = (float*)d_out;

    cudaFuncSetAttribute(mma_d2_kernel,
                         cudaFuncAttributeMaxDynamicSharedMemorySize, SMEM_P1);

    normalize_kernel<<<2 * (MASK_N / 8), 256>>>(f1, f2, mask1, mask2);
    dim3 grid(HW / 128, HW / 128, BATCH);
    mma_d2_kernel<<<grid, 256, SMEM_P1>>>(mask1, mask2);
    scan_kernel<<<BATCH * HW, 128>>>();
    refine_kernel<<<2048, 256>>>();
    topk_kernel<<<BATCH * 2, 512>>>(mask1, mask2, bk1, bk2, out);
}